// round 14
// baseline (speedup 1.0000x reference)
#include <cuda_runtime.h>
#include <cuda_bf16.h>
#include <mma.h>
#include <math.h>
#include <float.h>
#include <stdint.h>

using namespace nvcuda;

// ----------------------------------------------------------------------------
// GATv2 x2 + mean-pool + classifier, dense-pair formulation.
// N=201, E=40200 (+201 self loops), D=1024 = 8 heads x 128 ch.
// Weights/activations pre-split to bf16 hi/lo once (k_cvt); WMMA GEMM with
// 64x32 tiles / 256 blocks. Score 32x32; softmax pass; aggregation fp32 GEMM.
// ----------------------------------------------------------------------------

#define NN   201
#define EE   40200
#define DD   1024
#define HH   8
#define CC   128
#define NPJ  224
#define NPAD 204

// -------- scratch (device globals; no allocation allowed) -------------------
__device__ __align__(16) float g_XL[NPAD * DD];
__device__ __align__(16) float g_XR[NPAD * DD];
__device__ __align__(16) float g_H2[NPAD * DD];
__device__ __align__(16) float g_S [HH * NN * NPJ];   // scores -> alphas in place
__device__ int   g_cnt[NN * NPJ];     // statically zero; re-zeroed by k_pool
__device__ __align__(16) float g_avg[DD];
// bf16 hi/lo operands: W order [W1l, W1r, W2l, W2r]; X = x (L1) then H (L2)
__device__ __align__(16) __nv_bfloat16 g_Wh[4 * DD * DD];
__device__ __align__(16) __nv_bfloat16 g_Wl[4 * DD * DD];
__device__ __align__(16) __nv_bfloat16 g_Xh[NPAD * DD];   // rows >= NN stay 0
__device__ __align__(16) __nv_bfloat16 g_Xl[NPAD * DD];

__device__ __forceinline__ void cvt8(const float* v, __nv_bfloat16* hi, __nv_bfloat16* lo) {
#pragma unroll
    for (int e = 0; e < 8; e++) {
        hi[e] = __float2bfloat16(v[e]);
        lo[e] = __float2bfloat16(v[e] - __bfloat162float(hi[e]));
    }
}

// ---------------------------------------------------------------------------
// k_cvt: one launch at graph start.
//   blocks [0,2048)      : W1l/W1r/W2l/W2r fp32 -> bf16 hi/lo (512 blocks each)
//   blocks [2048,2149)   : x -> g_Xh/g_Xl
//   blocks [2149,2213)   : edge counting (stride loop; stride detect per block)
// ---------------------------------------------------------------------------
#define WCVT_BLK 2048
#define XCVT_BLK 101
#define CNT_BLK  64
#define CVT_GRID (WCVT_BLK + XCVT_BLK + CNT_BLK)

__global__ void __launch_bounds__(256) k_cvt(
    const float* __restrict__ x,
    const float* __restrict__ W1l, const float* __restrict__ W1r,
    const float* __restrict__ W2l, const float* __restrict__ W2r,
    const int* __restrict__ eb)
{
    const int bid = blockIdx.x;
    const int tid = threadIdx.x;

    if (bid < WCVT_BLK) {
        const int wsel = bid >> 9;
        const float* src = (wsel == 0) ? W1l : (wsel == 1) ? W1r
                         : (wsel == 2) ? W2l : W2r;
        const size_t off = (((size_t)(bid & 511)) * 256 + tid) * 8;
        float v[8];
        *(float4*)&v[0] = *(const float4*)(src + off);
        *(float4*)&v[4] = *(const float4*)(src + off + 4);
        __nv_bfloat16 hi[8], lo[8];
        cvt8(v, hi, lo);
        const size_t base = (size_t)wsel * DD * DD + off;
        *(uint4*)(g_Wh + base) = *(uint4*)hi;
        *(uint4*)(g_Wl + base) = *(uint4*)lo;
    } else if (bid < WCVT_BLK + XCVT_BLK) {
        const size_t off = (((size_t)(bid - WCVT_BLK)) * 256 + tid) * 8;
        if (off < (size_t)NN * DD) {
            float v[8];
            *(float4*)&v[0] = *(const float4*)(x + off);
            *(float4*)&v[4] = *(const float4*)(x + off + 4);
            __nv_bfloat16 hi[8], lo[8];
            cvt8(v, hi, lo);
            *(uint4*)(g_Xh + off) = *(uint4*)hi;
            *(uint4*)(g_Xl + off) = *(uint4*)lo;
        }
    } else {
        __shared__ int st_s;
        if (tid == 0) {
            int st = 2;  // int64: odd words zero for values < 2^31
            for (int e = 0; e < 64; e++)
                if (eb[2 * e + 1] != 0) { st = 1; break; }
            st_s = st;
        }
        __syncthreads();
        const int st = st_s;
        const int cb = bid - WCVT_BLK - XCVT_BLK;
        for (int e = cb * 256 + tid; e < EE + NN; e += CNT_BLK * 256) {
            if (e < EE) {
                int src = eb[e * st];
                int dst = eb[(EE + e) * st];
                atomicAdd(&g_cnt[dst * NPJ + src], 1);
            } else {
                int v = e - EE;
                atomicAdd(&g_cnt[v * NPJ + v], 1);
            }
        }
    }
}

// ---------------------------------------------------------------------------
// WMMA bf16 GEMM, 64m x 32n tiles, 128 threads, double-buffered.
// O[m][n] = sum_k X[m][k]*W[n][k] + b[n]; grid (4 m, 32 n, 2 sides) = 256.
// Warp w owns rows [w*16, w*16+16), both 16-col halves (2 C frags).
// ---------------------------------------------------------------------------
#define A_LDM 40
#define STG_A (64 * A_LDM)
#define STG_B (32 * A_LDM)
#define STG_ELEMS (2 * STG_A + 2 * STG_B)   // Ah | Al | Bh | Bl (bf16 elems)

__global__ void __launch_bounds__(128) k_gemm_mma(
    int layer, const float* __restrict__ bl, const float* __restrict__ br)
{
    __shared__ __align__(16) char smem_raw[2 * STG_ELEMS * 2];   // 30720 B

    const int side = blockIdx.z;
    const float* b = side ? br : bl;
    float*       O = side ? g_XR : g_XL;
    const size_t wbase = ((size_t)((layer << 1) | side)) * DD * DD;
    const int m0 = blockIdx.x * 64;
    const int n0 = blockIdx.y * 32;

    const int tid = threadIdx.x;
    const int wid = tid >> 5;

    wmma::fragment<wmma::accumulator, 16, 16, 16, float> c0, c1;
    wmma::fill_fragment(c0, 0.f);
    wmma::fill_fragment(c1, 0.f);

    // loaders: A = 64 rows x 32 k (2 uint4/thread), B = 32 rows x 32 k (1/thread)
    const int  ar = tid >> 1;             // 0..63
    const int  aq = (tid & 1) * 16;       // k offset: thread covers [aq, aq+16)
    const int  br2 = tid >> 2;            // 0..31
    const int  bq = (tid & 3) * 8;
    const bool av = (m0 + ar) < NN;
    const __nv_bfloat16* aH = g_Xh + (size_t)(m0 + ar) * DD + aq;
    const __nv_bfloat16* aL = g_Xl + (size_t)(m0 + ar) * DD + aq;
    const __nv_bfloat16* bH = g_Wh + wbase + (size_t)(n0 + br2) * DD + bq;
    const __nv_bfloat16* bL = g_Wl + wbase + (size_t)(n0 + br2) * DD + bq;

    const uint4 z4 = {0, 0, 0, 0};

    auto stage = [&](int buf, uint4 ah0, uint4 ah1, uint4 al0, uint4 al1,
                     uint4 bh, uint4 blv) {
        __nv_bfloat16* Ah = (__nv_bfloat16*)smem_raw + buf * STG_ELEMS;
        __nv_bfloat16* Al = Ah + STG_A;
        __nv_bfloat16* Bh = Al + STG_A;
        __nv_bfloat16* Bl = Bh + STG_B;
        *(uint4*)(Ah + ar * A_LDM + aq)     = ah0;
        *(uint4*)(Ah + ar * A_LDM + aq + 8) = ah1;
        *(uint4*)(Al + ar * A_LDM + aq)     = al0;
        *(uint4*)(Al + ar * A_LDM + aq + 8) = al1;
        *(uint4*)(Bh + br2 * A_LDM + bq) = bh;
        *(uint4*)(Bl + br2 * A_LDM + bq) = blv;
    };

    {
        uint4 ah0 = av ? *(const uint4*)(aH)     : z4;
        uint4 ah1 = av ? *(const uint4*)(aH + 8) : z4;
        uint4 al0 = av ? *(const uint4*)(aL)     : z4;
        uint4 al1 = av ? *(const uint4*)(aL + 8) : z4;
        uint4 bh  = *(const uint4*)(bH);
        uint4 blv = *(const uint4*)(bL);
        stage(0, ah0, ah1, al0, al1, bh, blv);
    }
    __syncthreads();

    const int NCHUNK = DD / 32;
    for (int kc = 0; kc < NCHUNK; kc++) {
        const int cur = kc & 1;

        uint4 ah0, ah1, al0, al1, bh, blv;
        const bool more = (kc + 1 < NCHUNK);
        if (more) {
            const int kb = (kc + 1) * 32;
            ah0 = av ? *(const uint4*)(aH + kb)     : z4;
            ah1 = av ? *(const uint4*)(aH + kb + 8) : z4;
            al0 = av ? *(const uint4*)(aL + kb)     : z4;
            al1 = av ? *(const uint4*)(aL + kb + 8) : z4;
            bh  = *(const uint4*)(bH + kb);
            blv = *(const uint4*)(bL + kb);
        }

        {
            __nv_bfloat16* Ah = (__nv_bfloat16*)smem_raw + cur * STG_ELEMS;
            __nv_bfloat16* Al = Ah + STG_A;
            __nv_bfloat16* Bh = Al + STG_A;
            __nv_bfloat16* Bl = Bh + STG_B;
#pragma unroll
            for (int ks = 0; ks < 2; ks++) {
                const int kk = ks * 16;
                wmma::fragment<wmma::matrix_a, 16, 16, 16, __nv_bfloat16, wmma::row_major> fah, fal;
                wmma::load_matrix_sync(fah, Ah + (wid * 16) * A_LDM + kk, A_LDM);
                wmma::load_matrix_sync(fal, Al + (wid * 16) * A_LDM + kk, A_LDM);

                wmma::fragment<wmma::matrix_b, 16, 16, 16, __nv_bfloat16, wmma::col_major> fbh, fbl;
                wmma::load_matrix_sync(fbh, Bh + 0 * A_LDM + kk, A_LDM);
                wmma::load_matrix_sync(fbl, Bl + 0 * A_LDM + kk, A_LDM);
                wmma::mma_sync(c0, fah, fbh, c0);
                wmma::mma_sync(c0, fah, fbl, c0);
                wmma::mma_sync(c0, fal, fbh, c0);

                wmma::load_matrix_sync(fbh, Bh + 16 * A_LDM + kk, A_LDM);
                wmma::load_matrix_sync(fbl, Bl + 16 * A_LDM + kk, A_LDM);
                wmma::mma_sync(c1, fah, fbh, c1);
                wmma::mma_sync(c1, fah, fbl, c1);
                wmma::mma_sync(c1, fal, fbh, c1);
            }
        }

        if (more) stage(cur ^ 1, ah0, ah1, al0, al1, bh, blv);
        __syncthreads();
    }

    // epilogue via smem (aliases staging), fused bias
    float* Cs = (float*)smem_raw;            // 64 x 40 fp32 = 10240 B
    wmma::store_matrix_sync(Cs + (wid * 16) * 40 + 0,  c0, 40, wmma::mem_row_major);
    wmma::store_matrix_sync(Cs + (wid * 16) * 40 + 16, c1, 40, wmma::mem_row_major);
    __syncthreads();

    const int m  = m0 + (tid >> 1);
    const int cb = (tid & 1) * 16;
    if (m < NN) {
        float* orow = O + (size_t)m * DD + n0 + cb;
        const float* bp = b + n0 + cb;
#pragma unroll
        for (int c4 = 0; c4 < 16; c4 += 4) {
            float4 vv = *(float4*)&Cs[(tid >> 1) * 40 + cb + c4];
            float4 bb = *(const float4*)(bp + c4);
            vv.x += bb.x; vv.y += bb.y; vv.z += bb.z; vv.w += bb.w;
            *(float4*)(orow + c4) = vv;
        }
    }
}

// ---------------------------------------------------------------------------
// Dense pairwise scores, 32x32 tiles / 128 threads, microtile 2i x 4j.
//   S[h,i,j] = P'(0.4*att) + 1.5*AL'   (AR term cancels in the softmax)
// grid = (7, 7, 8) = 392 blocks.
// ---------------------------------------------------------------------------
__global__ void __launch_bounds__(128) k_score(const float* __restrict__ att) {
    const int h   = blockIdx.z;
    const int i0  = blockIdx.x * 32;
    const int j0  = blockIdx.y * 32;
    const int tid = threadIdx.x;
    const int tx  = tid & 7;
    const int ty  = tid >> 3;
    const int lrow = tid >> 2;
    const int lq   = (tid & 3) << 2;

    __shared__ __align__(16) float att_s[CC];   // 0.4 * att
    __shared__ float AL_s[32];
    __shared__ float alp[32][4];
    __shared__ float As[16][32];
    __shared__ float Bs[16][32];

    if (tid < 32) {
        float4 a = *(const float4*)(att + h * CC + tid * 4);
        a.x *= 0.4f; a.y *= 0.4f; a.z *= 0.4f; a.w *= 0.4f;
        *(float4*)&att_s[tid * 4] = a;
    }
    __syncthreads();

    {
        int jj = tid >> 2, part = tid & 3;
        int j  = j0 + jj;
        float s = 0.f;
        if (j < NN) {
            const float4* xp4 = (const float4*)(g_XL + (size_t)j * DD + h * CC + part * 32);
#pragma unroll
            for (int q = 0; q < 8; q++) {
                float4 xv = xp4[q];
                const float* ap = att_s + part * 32 + q * 4;
                s = fmaf(ap[0], xv.x, s);
                s = fmaf(ap[1], xv.y, s);
                s = fmaf(ap[2], xv.z, s);
                s = fmaf(ap[3], xv.w, s);
            }
        }
        alp[jj][part] = s;
    }
    __syncthreads();
    if (tid < 32) AL_s[tid] = alp[tid][0] + alp[tid][1] + alp[tid][2] + alp[tid][3];
    __syncthreads();

    const int  gi = i0 + lrow;
    const int  gj = j0 + lrow;
    const bool iv = (gi < NN);
    const bool jv = (gj < NN);
    const float* xrp = g_XR + (size_t)gi * DD + h * CC;
    const float* xlp = g_XL + (size_t)gj * DD + h * CC;

    float acc[2][4];
#pragma unroll
    for (int i = 0; i < 2; i++)
#pragma unroll
        for (int j = 0; j < 4; j++) acc[i][j] = 0.f;

    float4 ra = iv ? *(const float4*)(xrp + lq) : make_float4(0, 0, 0, 0);
    float4 rb = jv ? *(const float4*)(xlp + lq) : make_float4(0, 0, 0, 0);

    for (int k0 = 0; k0 < CC; k0 += 16) {
        As[lq + 0][lrow] = ra.x; As[lq + 1][lrow] = ra.y;
        As[lq + 2][lrow] = ra.z; As[lq + 3][lrow] = ra.w;
        Bs[lq + 0][lrow] = rb.x; Bs[lq + 1][lrow] = rb.y;
        Bs[lq + 2][lrow] = rb.z; Bs[lq + 3][lrow] = rb.w;
        __syncthreads();

        if (k0 + 16 < CC) {
            ra = iv ? *(const float4*)(xrp + k0 + 16 + lq) : make_float4(0, 0, 0, 0);
            rb = jv ? *(const float4*)(xlp + k0 + 16 + lq) : make_float4(0, 0, 0, 0);
        }

#pragma unroll
        for (int k = 0; k < 16; k++) {
            float a0 = As[k][ty * 2 + 0];
            float a1 = As[k][ty * 2 + 1];
            float4 b4 = *(const float4*)&Bs[k][tx << 2];
            float bv[4] = {b4.x, b4.y, b4.z, b4.w};
            float ac = att_s[k0 + k];
#pragma unroll
            for (int j = 0; j < 4; j++) {
                float t0 = a0 + bv[j];
                float t1 = a1 + bv[j];
                acc[0][j] = fmaf(ac, fabsf(t0), acc[0][j]);
                acc[1][j] = fmaf(ac, fabsf(t1), acc[1][j]);
            }
        }
        __syncthreads();
    }

#pragma unroll
    for (int ii = 0; ii < 2; ii++) {
        int i = i0 + ty * 2 + ii;
        if (i >= NN) continue;
        float* row = g_S + (size_t)(h * NN + i) * NPJ;
#pragma unroll
        for (int jj = 0; jj < 4; jj++) {
            int j = j0 + (tx << 2) + jj;
            if (j < NN)
                row[j] = fmaf(1.5f, AL_s[(tx << 2) + jj], acc[ii][jj]);
        }
    }
}

// ---------------------------------------------------------------------------
// Alpha normalization in place (vectorized): g_S row -> softmax alphas.
// grid (26, 8), 256 threads; warp per destination row.
// ---------------------------------------------------------------------------
__global__ void __launch_bounds__(256) k_norm() {
    const int h    = blockIdx.y;
    const int i    = blockIdx.x * 8 + (threadIdx.x >> 5);
    const int lane = threadIdx.x & 31;
    if (i >= NN) return;

    float*     srow = g_S + (size_t)(h * NN + i) * NPJ;
    const int* crow = g_cnt + i * NPJ;

    const bool two = (lane < 24);
    float4 s0 = *(const float4*)(srow + lane * 4);
    int4   c0 = *(const int4*)(crow + lane * 4);
    float4 s1 = make_float4(0, 0, 0, 0);
    int4   c1 = make_int4(0, 0, 0, 0);
    if (two) {
        s1 = *(const float4*)(srow + 128 + lane * 4);
        c1 = *(const int4*)(crow + 128 + lane * 4);
    }

    float sv[8], cv[8];
    sv[0] = (c0.x > 0) ? s0.x : -1e30f; cv[0] = (float)c0.x;
    sv[1] = (c0.y > 0) ? s0.y : -1e30f; cv[1] = (float)c0.y;
    sv[2] = (c0.z > 0) ? s0.z : -1e30f; cv[2] = (float)c0.z;
    sv[3] = (c0.w > 0) ? s0.w : -1e30f; cv[3] = (float)c0.w;
    sv[4] = (c1.x > 0) ? s1.x : -1e30f; cv[4] = (float)c1.x;
    sv[5] = (c1.y > 0) ? s1.y : -1e30f; cv[5] = (float)c1.y;
    sv[6] = (c1.z > 0) ? s1.z : -1e30f; cv[6] = (float)c1.z;
    sv[7] = (c1.w > 0) ? s1.w : -1e30f; cv[7] = (float)c1.w;

    float mx = -FLT_MAX;
#pragma unroll
    for (int t = 0; t < 8; t++) mx = fmaxf(mx, sv[t]);
#pragma unroll
    for (int o = 16; o; o >>= 1) mx = fmaxf(mx, __shfl_xor_sync(0xffffffffu, mx, o));

    float ev[8];
    float ds = 0.f;
#pragma unroll
    for (int t = 0; t < 8; t++) { ev[t] = cv[t] * __expf(sv[t] - mx); ds += ev[t]; }
#pragma unroll
    for (int o = 16; o; o >>= 1) ds += __shfl_xor_sync(0xffffffffu, ds, o);
    float inv = 1.f / (ds + 1e-16f);

    float4 a0 = {ev[0] * inv, ev[1] * inv, ev[2] * inv, ev[3] * inv};
    *(float4*)(srow + lane * 4) = a0;
    if (two) {
        float4 a1 = {ev[4] * inv, ev[5] * inv, ev[6] * inv, ev[7] * inv};
        *(float4*)(srow + 128 + lane * 4) = a1;
    }
}

// ---------------------------------------------------------------------------
// Aggregation GEMM: OUT[i][h*CC+n] = sum_j alpha[h,i,j] * XL[j][h*CC+n] + bias
// Tile 32i x 32n; 128 threads, microtile 2i x 4n; grid (7,4,8) = 224 blocks.
// Layer 1 also writes the bf16 hi/lo twin of H into g_Xh/g_Xl for GEMM-2.
// ---------------------------------------------------------------------------
__global__ void __launch_bounds__(128) k_aggemm(const float* __restrict__ bias,
                                                int relu, int dst_sel) {
    float*    OUT = g_H2;
    const int h   = blockIdx.z;
    const int i0  = blockIdx.x * 32;
    const int n0  = blockIdx.y * 32;
    const int tid = threadIdx.x;
    const int tx  = tid & 7;
    const int ty  = tid >> 3;

    __shared__ float As[16][32];
    __shared__ float Bs[16][32];

    const int  ar  = tid & 31;
    const int  akq = (tid >> 5) << 2;
    const bool iv  = (i0 + ar) < NN;
    const float* arow = g_S + (size_t)(h * NN + i0 + ar) * NPJ;

    const int bk = tid >> 3;
    const int bn = (tid & 7) << 2;

    float acc[2][4];
#pragma unroll
    for (int i = 0; i < 2; i++)
#pragma unroll
        for (int j = 0; j < 4; j++) acc[i][j] = 0.f;

    float4 ra = iv ? *(const float4*)(arow + akq) : make_float4(0, 0, 0, 0);
    float4 rb = (bk < NN) ? *(const float4*)(g_XL + (size_t)bk * DD + h * CC + n0 + bn)
                          : make_float4(0, 0, 0, 0);

    for (int k0 = 0; k0 < NPJ; k0 += 16) {
        As[akq + 0][ar] = ra.x; As[akq + 1][ar] = ra.y;
        As[akq + 2][ar] = ra.z; As[akq + 3][ar] = ra.w;
        *(float4*)&Bs[bk][bn] = rb;
        __syncthreads();

        if (k0 + 16 < NPJ) {
            ra = iv ? *(const float4*)(arow + k0 + 16 + akq) : make_float4(0, 0, 0, 0);
            int jn = k0 + 16 + bk;
            rb = (jn < NN) ? *(const float4*)(g_XL + (size_t)jn * DD + h * CC + n0 + bn)
                           : make_float4(0, 0, 0, 0);
        }

#pragma unroll
        for (int k = 0; k < 16; k++) {
            float2 ap = *(const float2*)&As[k][ty * 2];
            float a0 = ap.x, a1 = ap.y;
            float4 v0 = *(const float4*)&Bs[k][tx * 4];
            acc[0][0] = fmaf(a0, v0.x, acc[0][0]);
            acc[0][1] = fmaf(a0, v0.y, acc[0][1]);
            acc[0][2] = fmaf(a0, v0.z, acc[0][2]);
            acc[0][3] = fmaf(a0, v0.w, acc[0][3]);
            acc[1][0] = fmaf(a1, v0.x, acc[1][0]);
            acc[1][1] = fmaf(a1, v0.y, acc[1][1]);
            acc[1][2] = fmaf(a1, v0.z, acc[1][2]);
            acc[1][3] = fmaf(a1, v0.w, acc[1][3]);
        }
        __syncthreads();
    }

#pragma unroll
    for (int ii = 0; ii < 2; ii++) {
        int i = i0 + ty * 2 + ii;
        if (i >= NN) continue;
        const int col = h * CC + n0 + tx * 4;
        const float* bp = bias + h * CC + n0;
        float4 o0 = {acc[ii][0], acc[ii][1], acc[ii][2], acc[ii][3]};
        float4 b0 = *(const float4*)(bp + tx * 4);
        o0.x += b0.x; o0.y += b0.y; o0.z += b0.z; o0.w += b0.w;
        if (relu) {
            o0.x = fmaxf(o0.x, 0.f); o0.y = fmaxf(o0.y, 0.f);
            o0.z = fmaxf(o0.z, 0.f); o0.w = fmaxf(o0.w, 0.f);
        }
        *(float4*)(OUT + (size_t)i * DD + col) = o0;
        if (!dst_sel) {
            float v[4] = {o0.x, o0.y, o0.z, o0.w};
            __nv_bfloat16 hi[4], lo[4];
#pragma unroll
            for (int e = 0; e < 4; e++) {
                hi[e] = __float2bfloat16(v[e]);
                lo[e] = __float2bfloat16(v[e] - __bfloat162float(hi[e]));
            }
            *(uint2*)(g_Xh + (size_t)i * DD + col) = *(uint2*)hi;
            *(uint2*)(g_Xl + (size_t)i * DD + col) = *(uint2*)lo;
        }
    }
}

// ---------------------------------------------------------------------------
// Pooling (8 blocks x 128): avg[d] = sum_i w_i * H2[i][d]; re-zeroes g_cnt.
// ---------------------------------------------------------------------------
__global__ void k_pool() {
    int d = blockIdx.x * blockDim.x + threadIdx.x;
    float s = 0.f;
#pragma unroll 8
    for (int i = 0; i < NN - 1; i++) s += g_H2[i * DD + d];
    s = s * (1.f / 300.f) + g_H2[(NN - 1) * DD + d] * (1.f / 3.f);
    g_avg[d] = s;
    for (int idx = d; idx < NN * NPJ; idx += 1024) g_cnt[idx] = 0;
}

// ---------------------------------------------------------------------------
// Classifier: out[c] = avg . clfW[c] + clfb[c]
// ---------------------------------------------------------------------------
__global__ void k_clf(const float* __restrict__ W, const float* __restrict__ b,
                      float* __restrict__ out) {
    __shared__ float red0[8], red1[8];
    int tid = threadIdx.x;
    float p0 = 0.f, p1 = 0.f;
    for (int d = tid; d < DD; d += 256) {
        float a = g_avg[d];
        p0 = fmaf(a, W[d], p0);
        p1 = fmaf(a, W[DD + d], p1);
    }
    for (int o = 16; o; o >>= 1) {
        p0 += __shfl_xor_sync(0xffffffffu, p0, o);
        p1 += __shfl_xor_sync(0xffffffffu, p1, o);
    }
    if ((tid & 31) == 0) { red0[tid >> 5] = p0; red1[tid >> 5] = p1; }
    __syncthreads();
    if (tid == 0) {
        float s0 = 0.f, s1 = 0.f;
        for (int w = 0; w < 8; w++) { s0 += red0[w]; s1 += red1[w]; }
        out[0] = s0 + b[0];
        out[1] = s1 + b[1];
    }
}

// ---------------------------------------------------------------------------
extern "C" void kernel_launch(void* const* d_in, const int* in_sizes, int n_in,
                              void* d_out, int out_size) {
    const float* x     = (const float*)d_in[0];
    const int*   ebuf  = (const int*)  d_in[1];
    const float* W1l   = (const float*)d_in[2];
    const float* b1l   = (const float*)d_in[3];
    const float* W1r   = (const float*)d_in[4];
    const float* b1r   = (const float*)d_in[5];
    const float* att1  = (const float*)d_in[6];
    const float* bias1 = (const float*)d_in[7];
    const float* W2l   = (const float*)d_in[8];
    const float* b2l   = (const float*)d_in[9];
    const float* W2r   = (const float*)d_in[10];
    const float* b2r   = (const float*)d_in[11];
    const float* att2  = (const float*)d_in[12];
    const float* bias2 = (const float*)d_in[13];
    const float* clfW  = (const float*)d_in[14];
    const float* clfb  = (const float*)d_in[15];
    float* out = (float*)d_out;

    dim3 gg(4, 32, 2);          // GEMM: m-tiles x n-tiles x {l,r} (256 blocks)
    dim3 gs(7, 7, HH);          // score
    dim3 gn(26, HH);            // norm
    dim3 ga(7, 4, HH);          // agg

    // convert weights + x to bf16 hi/lo; count edges (one launch)
    k_cvt<<<CVT_GRID, 256>>>(x, W1l, W1r, W2l, W2r, ebuf);

    // layer 1
    k_gemm_mma<<<gg, 128>>>(0, b1l, b1r);
    k_score   <<<gs, 128>>>(att1);
    k_norm    <<<gn, 256>>>();
    k_aggemm  <<<ga, 128>>>(bias1, /*relu=*/1, /*dst=*/0);   // writes bf16 H

    // layer 2
    k_gemm_mma<<<gg, 128>>>(1, b2l, b2r);
    k_score   <<<gs, 128>>>(att2);
    k_norm    <<<gn, 256>>>();
    k_aggemm  <<<ga, 128>>>(bias2, /*relu=*/0, /*dst=*/1);

    // pooling (+ g_cnt reset) and classifier
    k_pool<<<8, 128>>>();
    k_clf <<<1, 256>>>(clfW, clfb, out);
}

// round 15
// speedup vs baseline: 1.1408x; 1.1408x over previous
#include <cuda_runtime.h>
#include <cuda_bf16.h>
#include <mma.h>
#include <math.h>
#include <float.h>
#include <stdint.h>

using namespace nvcuda;

// ----------------------------------------------------------------------------
// GATv2 x2 + mean-pool + classifier, dense-pair formulation.
// N=201, E=40200 (+201 self loops), D=1024 = 8 heads x 128 ch.
// GEMMs: WMMA bf16 hi/lo split x3, K-SPLIT into two 512-chunks (2x blocks)
// with a tiny combine kernel. Edge-count fused into layer-1 GEMM launch.
// Score 32x32; vectorized softmax pass; aggregation fp32 GEMM 32x32.
// ----------------------------------------------------------------------------

#define NN   201
#define EE   40200
#define DD   1024
#define DK   512            // K per GEMM block (K-split)
#define HH   8
#define CC   128
#define NPJ  224
#define NPAD 204

// -------- scratch (device globals; no allocation allowed) -------------------
__device__ __align__(16) float g_XL [NPAD * DD];
__device__ __align__(16) float g_XR [NPAD * DD];
__device__ __align__(16) float g_XLb[NPAD * DD];   // K-half-1 partials
__device__ __align__(16) float g_XRb[NPAD * DD];
__device__ __align__(16) float g_H  [NPAD * DD];
__device__ __align__(16) float g_H2 [NPAD * DD];
__device__ __align__(16) float g_S  [HH * NN * NPJ];   // scores -> alphas
__device__ int   g_cnt[NN * NPJ];     // statically zero; re-zeroed by k_pool
__device__ __align__(16) float g_avg[DD];

// ---------------------------------------------------------------------------
// WMMA bf16 GEMM, double-buffered, K-split.
// z in [0,4): side = z&1, khalf = z>>1. z==4 (layer-1 only): edge counting.
// O_partial[m][n] = sum_{k in half} X[m][k]*W[n][k]  (+ b[n] for khalf 0)
// ---------------------------------------------------------------------------
#define A_LDM 40
#define C_LDM 72
#define BUF_ELEMS (4 * 64 * A_LDM)

__global__ void __launch_bounds__(256) k_gemm_mma(
    const float* __restrict__ Xin,
    const float* __restrict__ Wl, const float* __restrict__ bl,
    const float* __restrict__ Wr, const float* __restrict__ br,
    const int* __restrict__ eb)
{
    __shared__ __align__(16) char smem_raw[2 * BUF_ELEMS * 2];

    // ---- z==4: edge-count plane (64 blocks, layer-1 launch only) ----
    if (blockIdx.z == 4) {
        __shared__ int st_s;
        if (threadIdx.x == 0) {
            int st = 2;  // int64: odd words are high halves (zero for v < 2^31)
            for (int e = 0; e < 64; e++)
                if (eb[2 * e + 1] != 0) { st = 1; break; }
            st_s = st;
        }
        __syncthreads();
        const int st  = st_s;
        const int bid = blockIdx.y * 4 + blockIdx.x;       // 0..63
        for (int e = bid * 256 + threadIdx.x; e < EE + NN; e += 64 * 256) {
            if (e < EE) {
                int src = eb[e * st];
                int dst = eb[(EE + e) * st];
                atomicAdd(&g_cnt[dst * NPJ + src], 1);
            } else {
                int v = e - EE;                            // self loop
                atomicAdd(&g_cnt[v * NPJ + v], 1);
            }
        }
        return;
    }

    const float* X = Xin ? Xin : g_H;
    const int side = blockIdx.z & 1;
    const int kh   = blockIdx.z >> 1;
    const float* W = side ? Wr : Wl;
    const float* b = side ? br : bl;
    float*       O = kh ? (side ? g_XRb : g_XLb) : (side ? g_XR : g_XL);
    const int m0   = blockIdx.x * 64;
    const int n0   = blockIdx.y * 64;
    const int kofs = kh * DK;

    const int tid  = threadIdx.x;
    const int wid  = tid >> 5;
    const int wm   = wid >> 2;
    const int wn   = wid & 3;

    wmma::fragment<wmma::accumulator, 16, 16, 16, float> c0, c1;
    wmma::fill_fragment(c0, 0.f);
    wmma::fill_fragment(c1, 0.f);

    const int  lr = tid >> 2;
    const int  lq = (tid & 3) * 8;
    const bool av = (m0 + lr) < NN;
    const float* arow = X + (size_t)(m0 + lr) * DD + kofs + lq;
    const float* brow = W + (size_t)(n0 + lr) * DD + kofs + lq;

    auto stage = [&](int buf, float4 a0, float4 a1, float4 b0, float4 b1) {
        __nv_bfloat16* Ah = (__nv_bfloat16*)smem_raw + buf * BUF_ELEMS;
        __nv_bfloat16* Al = Ah + 64 * A_LDM;
        __nv_bfloat16* Bh = Al + 64 * A_LDM;
        __nv_bfloat16* Bl = Bh + 64 * A_LDM;
        float va[8] = {a0.x, a0.y, a0.z, a0.w, a1.x, a1.y, a1.z, a1.w};
        float vb[8] = {b0.x, b0.y, b0.z, b0.w, b1.x, b1.y, b1.z, b1.w};
        __nv_bfloat16 hi[8], lo[8];
#pragma unroll
        for (int e = 0; e < 8; e++) {
            hi[e] = __float2bfloat16(va[e]);
            lo[e] = __float2bfloat16(va[e] - __bfloat162float(hi[e]));
        }
        *(uint4*)(Ah + lr * A_LDM + lq) = *(uint4*)hi;
        *(uint4*)(Al + lr * A_LDM + lq) = *(uint4*)lo;
#pragma unroll
        for (int e = 0; e < 8; e++) {
            hi[e] = __float2bfloat16(vb[e]);
            lo[e] = __float2bfloat16(vb[e] - __bfloat162float(hi[e]));
        }
        *(uint4*)(Bh + lr * A_LDM + lq) = *(uint4*)hi;
        *(uint4*)(Bl + lr * A_LDM + lq) = *(uint4*)lo;
    };

    {
        float4 a0 = av ? *(const float4*)(arow)     : make_float4(0, 0, 0, 0);
        float4 a1 = av ? *(const float4*)(arow + 4) : make_float4(0, 0, 0, 0);
        float4 b0 = *(const float4*)(brow);
        float4 b1 = *(const float4*)(brow + 4);
        stage(0, a0, a1, b0, b1);
    }
    __syncthreads();

    const int NCHUNK = DK / 32;     // 16
    for (int kc = 0; kc < NCHUNK; kc++) {
        const int cur = kc & 1;

        float4 a0, a1, b0, b1;
        const bool more = (kc + 1 < NCHUNK);
        if (more) {
            const int kb = (kc + 1) * 32;
            a0 = av ? *(const float4*)(arow + kb)     : make_float4(0, 0, 0, 0);
            a1 = av ? *(const float4*)(arow + kb + 4) : make_float4(0, 0, 0, 0);
            b0 = *(const float4*)(brow + kb);
            b1 = *(const float4*)(brow + kb + 4);
        }

        {
            __nv_bfloat16* Ah = (__nv_bfloat16*)smem_raw + cur * BUF_ELEMS;
            __nv_bfloat16* Al = Ah + 64 * A_LDM;
            __nv_bfloat16* Bh = Al + 64 * A_LDM;
            __nv_bfloat16* Bl = Bh + 64 * A_LDM;
#pragma unroll
            for (int ks = 0; ks < 2; ks++) {
                const int kk = ks * 16;
                wmma::fragment<wmma::matrix_b, 16, 16, 16, __nv_bfloat16, wmma::col_major> fbh, fbl;
                wmma::load_matrix_sync(fbh, Bh + (wn * 16) * A_LDM + kk, A_LDM);
                wmma::load_matrix_sync(fbl, Bl + (wn * 16) * A_LDM + kk, A_LDM);

                wmma::fragment<wmma::matrix_a, 16, 16, 16, __nv_bfloat16, wmma::row_major> fah, fal;
                wmma::load_matrix_sync(fah, Ah + (wm * 32) * A_LDM + kk, A_LDM);
                wmma::load_matrix_sync(fal, Al + (wm * 32) * A_LDM + kk, A_LDM);
                wmma::mma_sync(c0, fah, fbh, c0);
                wmma::mma_sync(c0, fah, fbl, c0);
                wmma::mma_sync(c0, fal, fbh, c0);
                wmma::load_matrix_sync(fah, Ah + (wm * 32 + 16) * A_LDM + kk, A_LDM);
                wmma::load_matrix_sync(fal, Al + (wm * 32 + 16) * A_LDM + kk, A_LDM);
                wmma::mma_sync(c1, fah, fbh, c1);
                wmma::mma_sync(c1, fah, fbl, c1);
                wmma::mma_sync(c1, fal, fbh, c1);
            }
        }

        if (more) stage(cur ^ 1, a0, a1, b0, b1);
        __syncthreads();
    }

    float* Cs = (float*)smem_raw;
    wmma::store_matrix_sync(Cs + (wm * 32) * C_LDM + wn * 16, c0, C_LDM, wmma::mem_row_major);
    wmma::store_matrix_sync(Cs + (wm * 32 + 16) * C_LDM + wn * 16, c1, C_LDM, wmma::mem_row_major);
    __syncthreads();

    const int m = m0 + lr;
    if (m < NN) {
        const int cb = (tid & 3) * 16;
        float* orow = O + (size_t)m * DD + n0 + cb;
        const float* bp = b + n0 + cb;
#pragma unroll
        for (int c4 = 0; c4 < 16; c4 += 4) {
            float4 vv = *(float4*)&Cs[lr * C_LDM + cb + c4];
            if (kh == 0) {
                float4 bb = *(const float4*)(bp + c4);
                vv.x += bb.x; vv.y += bb.y; vv.z += bb.z; vv.w += bb.w;
            }
            *(float4*)(orow + c4) = vv;
        }
    }
}

// ---------------------------------------------------------------------------
// Combine K-split partials: g_XL += g_XLb; g_XR += g_XRb.
// 201 blocks x 256 threads; one float4 per thread per array.
// ---------------------------------------------------------------------------
__global__ void __launch_bounds__(256) k_comb() {
    const int idx = blockIdx.x * 256 + threadIdx.x;     // 51456 = 201*1024/4
    float4* xl = (float4*)g_XL;
    float4* xr = (float4*)g_XR;
    const float4* xlb = (const float4*)g_XLb;
    const float4* xrb = (const float4*)g_XRb;
    float4 a = xl[idx], b = xlb[idx];
    a.x += b.x; a.y += b.y; a.z += b.z; a.w += b.w;
    xl[idx] = a;
    float4 c = xr[idx], d = xrb[idx];
    c.x += d.x; c.y += d.y; c.z += d.z; c.w += d.w;
    xr[idx] = c;
}

// ---------------------------------------------------------------------------
// Dense pairwise scores, 32x32 tiles / 128 threads, microtile 2i x 4j.
//   S[h,i,j] = P'(0.4*att) + 1.5*AL'   (AR term cancels in the softmax)
// grid = (7, 7, 8) = 392 blocks.
// ---------------------------------------------------------------------------
__global__ void __launch_bounds__(128) k_score(const float* __restrict__ att) {
    const int h   = blockIdx.z;
    const int i0  = blockIdx.x * 32;
    const int j0  = blockIdx.y * 32;
    const int tid = threadIdx.x;
    const int tx  = tid & 7;
    const int ty  = tid >> 3;
    const int lrow = tid >> 2;
    const int lq   = (tid & 3) << 2;

    __shared__ __align__(16) float att_s[CC];   // 0.4 * att
    __shared__ float AL_s[32];
    __shared__ float alp[32][4];
    __shared__ float As[16][32];
    __shared__ float Bs[16][32];

    if (tid < 32) {
        float4 a = *(const float4*)(att + h * CC + tid * 4);
        a.x *= 0.4f; a.y *= 0.4f; a.z *= 0.4f; a.w *= 0.4f;
        *(float4*)&att_s[tid * 4] = a;
    }
    __syncthreads();

    {
        int jj = tid >> 2, part = tid & 3;
        int j  = j0 + jj;
        float s = 0.f;
        if (j < NN) {
            const float4* xp4 = (const float4*)(g_XL + (size_t)j * DD + h * CC + part * 32);
#pragma unroll
            for (int q = 0; q < 8; q++) {
                float4 xv = xp4[q];
                const float* ap = att_s + part * 32 + q * 4;
                s = fmaf(ap[0], xv.x, s);
                s = fmaf(ap[1], xv.y, s);
                s = fmaf(ap[2], xv.z, s);
                s = fmaf(ap[3], xv.w, s);
            }
        }
        alp[jj][part] = s;
    }
    __syncthreads();
    if (tid < 32) AL_s[tid] = alp[tid][0] + alp[tid][1] + alp[tid][2] + alp[tid][3];
    __syncthreads();

    const int  gi = i0 + lrow;
    const int  gj = j0 + lrow;
    const bool iv = (gi < NN);
    const bool jv = (gj < NN);
    const float* xrp = g_XR + (size_t)gi * DD + h * CC;
    const float* xlp = g_XL + (size_t)gj * DD + h * CC;

    float acc[2][4];
#pragma unroll
    for (int i = 0; i < 2; i++)
#pragma unroll
        for (int j = 0; j < 4; j++) acc[i][j] = 0.f;

    float4 ra = iv ? *(const float4*)(xrp + lq) : make_float4(0, 0, 0, 0);
    float4 rb = jv ? *(const float4*)(xlp + lq) : make_float4(0, 0, 0, 0);

    for (int k0 = 0; k0 < CC; k0 += 16) {
        As[lq + 0][lrow] = ra.x; As[lq + 1][lrow] = ra.y;
        As[lq + 2][lrow] = ra.z; As[lq + 3][lrow] = ra.w;
        Bs[lq + 0][lrow] = rb.x; Bs[lq + 1][lrow] = rb.y;
        Bs[lq + 2][lrow] = rb.z; Bs[lq + 3][lrow] = rb.w;
        __syncthreads();

        if (k0 + 16 < CC) {
            ra = iv ? *(const float4*)(xrp + k0 + 16 + lq) : make_float4(0, 0, 0, 0);
            rb = jv ? *(const float4*)(xlp + k0 + 16 + lq) : make_float4(0, 0, 0, 0);
        }

#pragma unroll
        for (int k = 0; k < 16; k++) {
            float a0 = As[k][ty * 2 + 0];
            float a1 = As[k][ty * 2 + 1];
            float4 b4 = *(const float4*)&Bs[k][tx << 2];
            float bv[4] = {b4.x, b4.y, b4.z, b4.w};
            float ac = att_s[k0 + k];
#pragma unroll
            for (int j = 0; j < 4; j++) {
                float t0 = a0 + bv[j];
                float t1 = a1 + bv[j];
                acc[0][j] = fmaf(ac, fabsf(t0), acc[0][j]);
                acc[1][j] = fmaf(ac, fabsf(t1), acc[1][j]);
            }
        }
        __syncthreads();
    }

#pragma unroll
    for (int ii = 0; ii < 2; ii++) {
        int i = i0 + ty * 2 + ii;
        if (i >= NN) continue;
        float* row = g_S + (size_t)(h * NN + i) * NPJ;
#pragma unroll
        for (int jj = 0; jj < 4; jj++) {
            int j = j0 + (tx << 2) + jj;
            if (j < NN)
                row[j] = fmaf(1.5f, AL_s[(tx << 2) + jj], acc[ii][jj]);
        }
    }
}

// ---------------------------------------------------------------------------
// Alpha normalization in place (vectorized): g_S row -> softmax alphas.
// grid (26, 8), 256 threads; warp per destination row.
// ---------------------------------------------------------------------------
__global__ void __launch_bounds__(256) k_norm() {
    const int h    = blockIdx.y;
    const int i    = blockIdx.x * 8 + (threadIdx.x >> 5);
    const int lane = threadIdx.x & 31;
    if (i >= NN) return;

    float*     srow = g_S + (size_t)(h * NN + i) * NPJ;
    const int* crow = g_cnt + i * NPJ;

    const bool two = (lane < 24);
    float4 s0 = *(const float4*)(srow + lane * 4);
    int4   c0 = *(const int4*)(crow + lane * 4);
    float4 s1 = make_float4(0, 0, 0, 0);
    int4   c1 = make_int4(0, 0, 0, 0);
    if (two) {
        s1 = *(const float4*)(srow + 128 + lane * 4);
        c1 = *(const int4*)(crow + 128 + lane * 4);
    }

    float sv[8], cv[8];
    sv[0] = (c0.x > 0) ? s0.x : -1e30f; cv[0] = (float)c0.x;
    sv[1] = (c0.y > 0) ? s0.y : -1e30f; cv[1] = (float)c0.y;
    sv[2] = (c0.z > 0) ? s0.z : -1e30f; cv[2] = (float)c0.z;
    sv[3] = (c0.w > 0) ? s0.w : -1e30f; cv[3] = (float)c0.w;
    sv[4] = (c1.x > 0) ? s1.x : -1e30f; cv[4] = (float)c1.x;
    sv[5] = (c1.y > 0) ? s1.y : -1e30f; cv[5] = (float)c1.y;
    sv[6] = (c1.z > 0) ? s1.z : -1e30f; cv[6] = (float)c1.z;
    sv[7] = (c1.w > 0) ? s1.w : -1e30f; cv[7] = (float)c1.w;

    float mx = -FLT_MAX;
#pragma unroll
    for (int t = 0; t < 8; t++) mx = fmaxf(mx, sv[t]);
#pragma unroll
    for (int o = 16; o; o >>= 1) mx = fmaxf(mx, __shfl_xor_sync(0xffffffffu, mx, o));

    float ev[8];
    float ds = 0.f;
#pragma unroll
    for (int t = 0; t < 8; t++) { ev[t] = cv[t] * __expf(sv[t] - mx); ds += ev[t]; }
#pragma unroll
    for (int o = 16; o; o >>= 1) ds += __shfl_xor_sync(0xffffffffu, ds, o);
    float inv = 1.f / (ds + 1e-16f);

    float4 a0 = {ev[0] * inv, ev[1] * inv, ev[2] * inv, ev[3] * inv};
    *(float4*)(srow + lane * 4) = a0;
    if (two) {
        float4 a1 = {ev[4] * inv, ev[5] * inv, ev[6] * inv, ev[7] * inv};
        *(float4*)(srow + 128 + lane * 4) = a1;
    }
}

// ---------------------------------------------------------------------------
// Aggregation GEMM: OUT[i][h*CC+n] = sum_j alpha[h,i,j] * XL[j][h*CC+n] + bias
// Tile 32i x 32n, K = NPJ = 224; 128 threads, microtile 2i x 4n.
// grid = (7 i-tiles, 4 n-tiles, 8 heads) = 224 blocks.
// ---------------------------------------------------------------------------
__global__ void __launch_bounds__(128) k_aggemm(const float* __restrict__ bias,
                                                int relu, int dst_sel) {
    float*    OUT = dst_sel ? g_H2 : g_H;
    const int h   = blockIdx.z;
    const int i0  = blockIdx.x * 32;
    const int n0  = blockIdx.y * 32;
    const int tid = threadIdx.x;
    const int tx  = tid & 7;
    const int ty  = tid >> 3;

    __shared__ float As[16][32];
    __shared__ float Bs[16][32];

    const int  ar  = tid & 31;
    const int  akq = (tid >> 5) << 2;
    const bool iv  = (i0 + ar) < NN;
    const float* arow = g_S + (size_t)(h * NN + i0 + ar) * NPJ;

    const int bk = tid >> 3;
    const int bn = (tid & 7) << 2;

    float acc[2][4];
#pragma unroll
    for (int i = 0; i < 2; i++)
#pragma unroll
        for (int j = 0; j < 4; j++) acc[i][j] = 0.f;

    float4 ra = iv ? *(const float4*)(arow + akq) : make_float4(0, 0, 0, 0);
    float4 rb = (bk < NN) ? *(const float4*)(g_XL + (size_t)bk * DD + h * CC + n0 + bn)
                          : make_float4(0, 0, 0, 0);

    for (int k0 = 0; k0 < NPJ; k0 += 16) {
        As[akq + 0][ar] = ra.x; As[akq + 1][ar] = ra.y;
        As[akq + 2][ar] = ra.z; As[akq + 3][ar] = ra.w;
        *(float4*)&Bs[bk][bn] = rb;
        __syncthreads();

        if (k0 + 16 < NPJ) {
            ra = iv ? *(const float4*)(arow + k0 + 16 + akq) : make_float4(0, 0, 0, 0);
            int jn = k0 + 16 + bk;
            rb = (jn < NN) ? *(const float4*)(g_XL + (size_t)jn * DD + h * CC + n0 + bn)
                           : make_float4(0, 0, 0, 0);
        }

#pragma unroll
        for (int k = 0; k < 16; k++) {
            float2 ap = *(const float2*)&As[k][ty * 2];
            float a0 = ap.x, a1 = ap.y;
            float4 v0 = *(const float4*)&Bs[k][tx * 4];
            acc[0][0] = fmaf(a0, v0.x, acc[0][0]);
            acc[0][1] = fmaf(a0, v0.y, acc[0][1]);
            acc[0][2] = fmaf(a0, v0.z, acc[0][2]);
            acc[0][3] = fmaf(a0, v0.w, acc[0][3]);
            acc[1][0] = fmaf(a1, v0.x, acc[1][0]);
            acc[1][1] = fmaf(a1, v0.y, acc[1][1]);
            acc[1][2] = fmaf(a1, v0.z, acc[1][2]);
            acc[1][3] = fmaf(a1, v0.w, acc[1][3]);
        }
        __syncthreads();
    }

#pragma unroll
    for (int ii = 0; ii < 2; ii++) {
        int i = i0 + ty * 2 + ii;
        if (i >= NN) continue;
        float* orow = OUT + (size_t)i * DD + h * CC + n0;
        const float* bp = bias + h * CC + n0;
        float4 o0 = {acc[ii][0], acc[ii][1], acc[ii][2], acc[ii][3]};
        float4 b0 = *(const float4*)(bp + tx * 4);
        o0.x += b0.x; o0.y += b0.y; o0.z += b0.z; o0.w += b0.w;
        if (relu) {
            o0.x = fmaxf(o0.x, 0.f); o0.y = fmaxf(o0.y, 0.f);
            o0.z = fmaxf(o0.z, 0.f); o0.w = fmaxf(o0.w, 0.f);
        }
        *(float4*)(orow + tx * 4) = o0;
    }
}

// ---------------------------------------------------------------------------
// Pooling (8 blocks x 128): avg[d] = sum_i w_i * H2[i][d]; re-zeroes g_cnt.
// ---------------------------------------------------------------------------
__global__ void k_pool() {
    int d = blockIdx.x * blockDim.x + threadIdx.x;
    float s = 0.f;
#pragma unroll 8
    for (int i = 0; i < NN - 1; i++) s += g_H2[i * DD + d];
    s = s * (1.f / 300.f) + g_H2[(NN - 1) * DD + d] * (1.f / 3.f);
    g_avg[d] = s;
    for (int idx = d; idx < NN * NPJ; idx += 1024) g_cnt[idx] = 0;
}

// ---------------------------------------------------------------------------
// Classifier: out[c] = avg . clfW[c] + clfb[c]
// ---------------------------------------------------------------------------
__global__ void k_clf(const float* __restrict__ W, const float* __restrict__ b,
                      float* __restrict__ out) {
    __shared__ float red0[8], red1[8];
    int tid = threadIdx.x;
    float p0 = 0.f, p1 = 0.f;
    for (int d = tid; d < DD; d += 256) {
        float a = g_avg[d];
        p0 = fmaf(a, W[d], p0);
        p1 = fmaf(a, W[DD + d], p1);
    }
    for (int o = 16; o; o >>= 1) {
        p0 += __shfl_xor_sync(0xffffffffu, p0, o);
        p1 += __shfl_xor_sync(0xffffffffu, p1, o);
    }
    if ((tid & 31) == 0) { red0[tid >> 5] = p0; red1[tid >> 5] = p1; }
    __syncthreads();
    if (tid == 0) {
        float s0 = 0.f, s1 = 0.f;
        for (int w = 0; w < 8; w++) { s0 += red0[w]; s1 += red1[w]; }
        out[0] = s0 + b[0];
        out[1] = s1 + b[1];
    }
}

// ---------------------------------------------------------------------------
extern "C" void kernel_launch(void* const* d_in, const int* in_sizes, int n_in,
                              void* d_out, int out_size) {
    const float* x     = (const float*)d_in[0];
    const int*   ebuf  = (const int*)  d_in[1];
    const float* W1l   = (const float*)d_in[2];
    const float* b1l   = (const float*)d_in[3];
    const float* W1r   = (const float*)d_in[4];
    const float* b1r   = (const float*)d_in[5];
    const float* att1  = (const float*)d_in[6];
    const float* bias1 = (const float*)d_in[7];
    const float* W2l   = (const float*)d_in[8];
    const float* b2l   = (const float*)d_in[9];
    const float* W2r   = (const float*)d_in[10];
    const float* b2r   = (const float*)d_in[11];
    const float* att2  = (const float*)d_in[12];
    const float* bias2 = (const float*)d_in[13];
    const float* clfW  = (const float*)d_in[14];
    const float* clfb  = (const float*)d_in[15];
    float* out = (float*)d_out;

    dim3 gg1(4, 16, 5);         // GEMM l/r x 2 K-halves + count plane (layer 1)
    dim3 gg2(4, 16, 4);         // GEMM l/r x 2 K-halves (layer 2)
    dim3 gs(7, 7, HH);          // score
    dim3 gn(26, HH);            // norm
    dim3 ga(7, 4, HH);          // agg

    // layer 1 (edge counting fused into the GEMM launch)
    k_gemm_mma<<<gg1, 256>>>(x, W1l, b1l, W1r, b1r, ebuf);
    k_comb    <<<201, 256>>>();
    k_score   <<<gs, 128>>>(att1);
    k_norm    <<<gn, 256>>>();
    k_aggemm  <<<ga, 128>>>(bias1, /*relu=*/1, /*dst=*/0);

    // layer 2
    k_gemm_mma<<<gg2, 256>>>(nullptr, W2l, b2l, W2r, b2r, nullptr);
    k_comb    <<<201, 256>>>();
    k_score   <<<gs, 128>>>(att2);
    k_norm    <<<gn, 256>>>();
    k_aggemm  <<<ga, 128>>>(bias2, /*relu=*/0, /*dst=*/1);

    // pooling (+ g_cnt reset) and classifier
    k_pool<<<8, 128>>>();
    k_clf <<<1, 256>>>(clfW, clfb, out);
}

// round 16
// speedup vs baseline: 1.1433x; 1.0022x over previous
#include <cuda_runtime.h>
#include <cuda_bf16.h>
#include <mma.h>
#include <math.h>
#include <float.h>
#include <stdint.h>

using namespace nvcuda;

// ----------------------------------------------------------------------------
// GATv2 x2 + mean-pool + classifier, dense-pair formulation.
// N=201, E=40200 (+201 self loops), D=1024 = 8 heads x 128 ch.
// GEMMs: WMMA bf16 hi/lo split x3 (edge-count fused into layer-1 launch).
// Score 32x32 BK32; vectorized softmax pass; aggregation fp32 GEMM 32x32 BK32.
// ----------------------------------------------------------------------------

#define NN   201
#define EE   40200
#define DD   1024
#define HH   8
#define CC   128
#define NPJ  224
#define NPAD 204

// -------- scratch (device globals; no allocation allowed) -------------------
__device__ __align__(16) float g_XL[NPAD * DD];
__device__ __align__(16) float g_XR[NPAD * DD];
__device__ __align__(16) float g_H [NPAD * DD];
__device__ __align__(16) float g_H2[NPAD * DD];
__device__ __align__(16) float g_S [HH * NN * NPJ];   // scores -> alphas in place
__device__ int   g_cnt[NN * NPJ];     // statically zero; re-zeroed by k_pool
__device__ __align__(16) float g_avg[DD];

// ---------------------------------------------------------------------------
// WMMA bf16 GEMM, double-buffered: O[m][n] = sum_k X[m][k]*W[n][k] + b[n]
// grid z: 0/1 = {l,r} GEMM side; z==2 (layer-1 only) = edge-count plane.
// ---------------------------------------------------------------------------
#define A_LDM 40
#define C_LDM 72
#define BUF_ELEMS (4 * 64 * A_LDM)

__global__ void __launch_bounds__(256) k_gemm_mma(
    const float* __restrict__ Xin,
    const float* __restrict__ Wl, const float* __restrict__ bl,
    const float* __restrict__ Wr, const float* __restrict__ br,
    const int* __restrict__ eb)
{
    __shared__ __align__(16) char smem_raw[2 * BUF_ELEMS * 2];

    // ---- z==2: edge-count plane (64 blocks, layer-1 launch only) ----
    if (blockIdx.z == 2) {
        __shared__ int st_s;
        if (threadIdx.x == 0) {
            int st = 2;  // int64: odd words are high halves (zero for v < 2^31)
            for (int e = 0; e < 64; e++)
                if (eb[2 * e + 1] != 0) { st = 1; break; }
            st_s = st;
        }
        __syncthreads();
        const int st  = st_s;
        const int bid = blockIdx.y * 4 + blockIdx.x;       // 0..63
        for (int e = bid * 256 + threadIdx.x; e < EE + NN; e += 64 * 256) {
            if (e < EE) {
                int src = eb[e * st];
                int dst = eb[(EE + e) * st];
                atomicAdd(&g_cnt[dst * NPJ + src], 1);
            } else {
                int v = e - EE;                            // self loop
                atomicAdd(&g_cnt[v * NPJ + v], 1);
            }
        }
        return;
    }

    const float* X = Xin ? Xin : g_H;
    const int side = blockIdx.z;
    const float* W = side ? Wr : Wl;
    const float* b = side ? br : bl;
    float*       O = side ? g_XR : g_XL;
    const int m0 = blockIdx.x * 64;
    const int n0 = blockIdx.y * 64;

    const int tid  = threadIdx.x;
    const int wid  = tid >> 5;
    const int wm   = wid >> 2;
    const int wn   = wid & 3;

    wmma::fragment<wmma::accumulator, 16, 16, 16, float> c0, c1;
    wmma::fill_fragment(c0, 0.f);
    wmma::fill_fragment(c1, 0.f);

    const int  lr = tid >> 2;
    const int  lq = (tid & 3) * 8;
    const bool av = (m0 + lr) < NN;
    const float* arow = X + (size_t)(m0 + lr) * DD + lq;
    const float* brow = W + (size_t)(n0 + lr) * DD + lq;

    auto stage = [&](int buf, float4 a0, float4 a1, float4 b0, float4 b1) {
        __nv_bfloat16* Ah = (__nv_bfloat16*)smem_raw + buf * BUF_ELEMS;
        __nv_bfloat16* Al = Ah + 64 * A_LDM;
        __nv_bfloat16* Bh = Al + 64 * A_LDM;
        __nv_bfloat16* Bl = Bh + 64 * A_LDM;
        float va[8] = {a0.x, a0.y, a0.z, a0.w, a1.x, a1.y, a1.z, a1.w};
        float vb[8] = {b0.x, b0.y, b0.z, b0.w, b1.x, b1.y, b1.z, b1.w};
        __nv_bfloat16 hi[8], lo[8];
#pragma unroll
        for (int e = 0; e < 8; e++) {
            hi[e] = __float2bfloat16(va[e]);
            lo[e] = __float2bfloat16(va[e] - __bfloat162float(hi[e]));
        }
        *(uint4*)(Ah + lr * A_LDM + lq) = *(uint4*)hi;
        *(uint4*)(Al + lr * A_LDM + lq) = *(uint4*)lo;
#pragma unroll
        for (int e = 0; e < 8; e++) {
            hi[e] = __float2bfloat16(vb[e]);
            lo[e] = __float2bfloat16(vb[e] - __bfloat162float(hi[e]));
        }
        *(uint4*)(Bh + lr * A_LDM + lq) = *(uint4*)hi;
        *(uint4*)(Bl + lr * A_LDM + lq) = *(uint4*)lo;
    };

    {
        float4 a0 = av ? *(const float4*)(arow)     : make_float4(0, 0, 0, 0);
        float4 a1 = av ? *(const float4*)(arow + 4) : make_float4(0, 0, 0, 0);
        float4 b0 = *(const float4*)(brow);
        float4 b1 = *(const float4*)(brow + 4);
        stage(0, a0, a1, b0, b1);
    }
    __syncthreads();

    const int NCHUNK = DD / 32;
    for (int kc = 0; kc < NCHUNK; kc++) {
        const int cur = kc & 1;

        float4 a0, a1, b0, b1;
        const bool more = (kc + 1 < NCHUNK);
        if (more) {
            const int kb = (kc + 1) * 32;
            a0 = av ? *(const float4*)(arow + kb)     : make_float4(0, 0, 0, 0);
            a1 = av ? *(const float4*)(arow + kb + 4) : make_float4(0, 0, 0, 0);
            b0 = *(const float4*)(brow + kb);
            b1 = *(const float4*)(brow + kb + 4);
        }

        {
            __nv_bfloat16* Ah = (__nv_bfloat16*)smem_raw + cur * BUF_ELEMS;
            __nv_bfloat16* Al = Ah + 64 * A_LDM;
            __nv_bfloat16* Bh = Al + 64 * A_LDM;
            __nv_bfloat16* Bl = Bh + 64 * A_LDM;
#pragma unroll
            for (int ks = 0; ks < 2; ks++) {
                const int kk = ks * 16;
                wmma::fragment<wmma::matrix_b, 16, 16, 16, __nv_bfloat16, wmma::col_major> fbh, fbl;
                wmma::load_matrix_sync(fbh, Bh + (wn * 16) * A_LDM + kk, A_LDM);
                wmma::load_matrix_sync(fbl, Bl + (wn * 16) * A_LDM + kk, A_LDM);

                wmma::fragment<wmma::matrix_a, 16, 16, 16, __nv_bfloat16, wmma::row_major> fah, fal;
                wmma::load_matrix_sync(fah, Ah + (wm * 32) * A_LDM + kk, A_LDM);
                wmma::load_matrix_sync(fal, Al + (wm * 32) * A_LDM + kk, A_LDM);
                wmma::mma_sync(c0, fah, fbh, c0);
                wmma::mma_sync(c0, fah, fbl, c0);
                wmma::mma_sync(c0, fal, fbh, c0);
                wmma::load_matrix_sync(fah, Ah + (wm * 32 + 16) * A_LDM + kk, A_LDM);
                wmma::load_matrix_sync(fal, Al + (wm * 32 + 16) * A_LDM + kk, A_LDM);
                wmma::mma_sync(c1, fah, fbh, c1);
                wmma::mma_sync(c1, fah, fbl, c1);
                wmma::mma_sync(c1, fal, fbh, c1);
            }
        }

        if (more) stage(cur ^ 1, a0, a1, b0, b1);
        __syncthreads();
    }

    float* Cs = (float*)smem_raw;
    wmma::store_matrix_sync(Cs + (wm * 32) * C_LDM + wn * 16, c0, C_LDM, wmma::mem_row_major);
    wmma::store_matrix_sync(Cs + (wm * 32 + 16) * C_LDM + wn * 16, c1, C_LDM, wmma::mem_row_major);
    __syncthreads();

    const int m = m0 + lr;
    if (m < NN) {
        const int cb = (tid & 3) * 16;
        float* orow = O + (size_t)m * DD + n0 + cb;
        const float* bp = b + n0 + cb;
#pragma unroll
        for (int c4 = 0; c4 < 16; c4 += 4) {
            float4 vv = *(float4*)&Cs[lr * C_LDM + cb + c4];
            float4 bb = *(const float4*)(bp + c4);
            vv.x += bb.x; vv.y += bb.y; vv.z += bb.z; vv.w += bb.w;
            *(float4*)(orow + c4) = vv;
        }
    }
}

// ---------------------------------------------------------------------------
// Dense pairwise scores, 32x32 tiles / 128 threads, BK=32, microtile 2i x 4j.
//   S[h,i,j] = P'(0.4*att) + 1.5*AL'   (AR term cancels in the softmax)
// grid = (7, 7, 8) = 392 blocks. 4 K-chunks -> 8 syncs (was 16).
// ---------------------------------------------------------------------------
__global__ void __launch_bounds__(128) k_score(const float* __restrict__ att) {
    const int h   = blockIdx.z;
    const int i0  = blockIdx.x * 32;
    const int j0  = blockIdx.y * 32;
    const int tid = threadIdx.x;
    const int tx  = tid & 7;
    const int ty  = tid >> 3;
    const int lrow = tid >> 2;        // 0..31
    const int lq8  = (tid & 3) << 3;  // 0,8,16,24

    __shared__ __align__(16) float att_s[CC];   // 0.4 * att
    __shared__ float AL_s[32];
    __shared__ float alp[32][4];
    __shared__ float As[32][32];
    __shared__ float Bs[32][32];

    if (tid < 32) {
        float4 a = *(const float4*)(att + h * CC + tid * 4);
        a.x *= 0.4f; a.y *= 0.4f; a.z *= 0.4f; a.w *= 0.4f;
        *(float4*)&att_s[tid * 4] = a;
    }
    __syncthreads();

    {
        int jj = tid >> 2, part = tid & 3;
        int j  = j0 + jj;
        float s = 0.f;
        if (j < NN) {
            const float4* xp4 = (const float4*)(g_XL + (size_t)j * DD + h * CC + part * 32);
#pragma unroll
            for (int q = 0; q < 8; q++) {
                float4 xv = xp4[q];
                const float* ap = att_s + part * 32 + q * 4;
                s = fmaf(ap[0], xv.x, s);
                s = fmaf(ap[1], xv.y, s);
                s = fmaf(ap[2], xv.z, s);
                s = fmaf(ap[3], xv.w, s);
            }
        }
        alp[jj][part] = s;
    }
    __syncthreads();
    if (tid < 32) AL_s[tid] = alp[tid][0] + alp[tid][1] + alp[tid][2] + alp[tid][3];
    __syncthreads();

    const int  gi = i0 + lrow;
    const int  gj = j0 + lrow;
    const bool iv = (gi < NN);
    const bool jv = (gj < NN);
    const float* xrp = g_XR + (size_t)gi * DD + h * CC;
    const float* xlp = g_XL + (size_t)gj * DD + h * CC;

    float acc[2][4];
#pragma unroll
    for (int i = 0; i < 2; i++)
#pragma unroll
        for (int j = 0; j < 4; j++) acc[i][j] = 0.f;

    const float4 z4 = make_float4(0, 0, 0, 0);
    float4 ra0 = iv ? *(const float4*)(xrp + lq8)     : z4;
    float4 ra1 = iv ? *(const float4*)(xrp + lq8 + 4) : z4;
    float4 rb0 = jv ? *(const float4*)(xlp + lq8)     : z4;
    float4 rb1 = jv ? *(const float4*)(xlp + lq8 + 4) : z4;

    for (int k0 = 0; k0 < CC; k0 += 32) {
        As[lq8 + 0][lrow] = ra0.x; As[lq8 + 1][lrow] = ra0.y;
        As[lq8 + 2][lrow] = ra0.z; As[lq8 + 3][lrow] = ra0.w;
        As[lq8 + 4][lrow] = ra1.x; As[lq8 + 5][lrow] = ra1.y;
        As[lq8 + 6][lrow] = ra1.z; As[lq8 + 7][lrow] = ra1.w;
        Bs[lq8 + 0][lrow] = rb0.x; Bs[lq8 + 1][lrow] = rb0.y;
        Bs[lq8 + 2][lrow] = rb0.z; Bs[lq8 + 3][lrow] = rb0.w;
        Bs[lq8 + 4][lrow] = rb1.x; Bs[lq8 + 5][lrow] = rb1.y;
        Bs[lq8 + 6][lrow] = rb1.z; Bs[lq8 + 7][lrow] = rb1.w;
        __syncthreads();

        if (k0 + 32 < CC) {
            const int kb = k0 + 32;
            ra0 = iv ? *(const float4*)(xrp + kb + lq8)     : z4;
            ra1 = iv ? *(const float4*)(xrp + kb + lq8 + 4) : z4;
            rb0 = jv ? *(const float4*)(xlp + kb + lq8)     : z4;
            rb1 = jv ? *(const float4*)(xlp + kb + lq8 + 4) : z4;
        }

#pragma unroll
        for (int k = 0; k < 32; k++) {
            float a0 = As[k][ty * 2 + 0];
            float a1 = As[k][ty * 2 + 1];
            float4 b4 = *(const float4*)&Bs[k][tx << 2];
            float bv[4] = {b4.x, b4.y, b4.z, b4.w};
            float ac = att_s[k0 + k];
#pragma unroll
            for (int j = 0; j < 4; j++) {
                float t0 = a0 + bv[j];
                float t1 = a1 + bv[j];
                acc[0][j] = fmaf(ac, fabsf(t0), acc[0][j]);
                acc[1][j] = fmaf(ac, fabsf(t1), acc[1][j]);
            }
        }
        __syncthreads();
    }

#pragma unroll
    for (int ii = 0; ii < 2; ii++) {
        int i = i0 + ty * 2 + ii;
        if (i >= NN) continue;
        float* row = g_S + (size_t)(h * NN + i) * NPJ;
#pragma unroll
        for (int jj = 0; jj < 4; jj++) {
            int j = j0 + (tx << 2) + jj;
            if (j < NN)
                row[j] = fmaf(1.5f, AL_s[(tx << 2) + jj], acc[ii][jj]);
        }
    }
}

// ---------------------------------------------------------------------------
// Alpha normalization in place (vectorized): g_S row -> softmax alphas.
// grid (26, 8), 256 threads; warp per destination row.
// ---------------------------------------------------------------------------
__global__ void __launch_bounds__(256) k_norm() {
    const int h    = blockIdx.y;
    const int i    = blockIdx.x * 8 + (threadIdx.x >> 5);
    const int lane = threadIdx.x & 31;
    if (i >= NN) return;

    float*     srow = g_S + (size_t)(h * NN + i) * NPJ;
    const int* crow = g_cnt + i * NPJ;

    const bool two = (lane < 24);
    float4 s0 = *(const float4*)(srow + lane * 4);
    int4   c0 = *(const int4*)(crow + lane * 4);
    float4 s1 = make_float4(0, 0, 0, 0);
    int4   c1 = make_int4(0, 0, 0, 0);
    if (two) {
        s1 = *(const float4*)(srow + 128 + lane * 4);
        c1 = *(const int4*)(crow + 128 + lane * 4);
    }

    float sv[8], cv[8];
    sv[0] = (c0.x > 0) ? s0.x : -1e30f; cv[0] = (float)c0.x;
    sv[1] = (c0.y > 0) ? s0.y : -1e30f; cv[1] = (float)c0.y;
    sv[2] = (c0.z > 0) ? s0.z : -1e30f; cv[2] = (float)c0.z;
    sv[3] = (c0.w > 0) ? s0.w : -1e30f; cv[3] = (float)c0.w;
    sv[4] = (c1.x > 0) ? s1.x : -1e30f; cv[4] = (float)c1.x;
    sv[5] = (c1.y > 0) ? s1.y : -1e30f; cv[5] = (float)c1.y;
    sv[6] = (c1.z > 0) ? s1.z : -1e30f; cv[6] = (float)c1.z;
    sv[7] = (c1.w > 0) ? s1.w : -1e30f; cv[7] = (float)c1.w;

    float mx = -FLT_MAX;
#pragma unroll
    for (int t = 0; t < 8; t++) mx = fmaxf(mx, sv[t]);
#pragma unroll
    for (int o = 16; o; o >>= 1) mx = fmaxf(mx, __shfl_xor_sync(0xffffffffu, mx, o));

    float ev[8];
    float ds = 0.f;
#pragma unroll
    for (int t = 0; t < 8; t++) { ev[t] = cv[t] * __expf(sv[t] - mx); ds += ev[t]; }
#pragma unroll
    for (int o = 16; o; o >>= 1) ds += __shfl_xor_sync(0xffffffffu, ds, o);
    float inv = 1.f / (ds + 1e-16f);

    float4 a0 = {ev[0] * inv, ev[1] * inv, ev[2] * inv, ev[3] * inv};
    *(float4*)(srow + lane * 4) = a0;
    if (two) {
        float4 a1 = {ev[4] * inv, ev[5] * inv, ev[6] * inv, ev[7] * inv};
        *(float4*)(srow + 128 + lane * 4) = a1;
    }
}

// ---------------------------------------------------------------------------
// Aggregation GEMM: OUT[i][h*CC+n] = sum_j alpha[h,i,j] * XL[j][h*CC+n] + bias
// Tile 32i x 32n, K = NPJ = 224, BK=32; 128 threads, microtile 2i x 4n.
// grid = (7 i-tiles, 4 n-tiles, 8 heads) = 224 blocks. 7 chunks -> 14 syncs.
// ---------------------------------------------------------------------------
__global__ void __launch_bounds__(128) k_aggemm(const float* __restrict__ bias,
                                                int relu, int dst_sel) {
    float*    OUT = dst_sel ? g_H2 : g_H;
    const int h   = blockIdx.z;
    const int i0  = blockIdx.x * 32;
    const int n0  = blockIdx.y * 32;
    const int tid = threadIdx.x;
    const int tx  = tid & 7;
    const int ty  = tid >> 3;

    __shared__ float As[32][32];      // alpha chunk [k][i]
    __shared__ float Bs[32][32];      // XL    chunk [k][n]

    // A staging: ar = i row (32), ak8 = k octet offset
    const int  ar  = tid & 31;
    const int  ak8 = (tid >> 5) << 3;     // 0,8,16,24
    const bool iv  = (i0 + ar) < NN;
    const float* arow = g_S + (size_t)(h * NN + i0 + ar) * NPJ;

    // B staging: rows bk and bk+16, bn = n quad
    const int bk = tid >> 3;              // 0..15
    const int bn = (tid & 7) << 2;        // 0,4,...,28

    float acc[2][4];
#pragma unroll
    for (int i = 0; i < 2; i++)
#pragma unroll
        for (int j = 0; j < 4; j++) acc[i][j] = 0.f;

    const float4 z4 = make_float4(0, 0, 0, 0);
    float4 ra0 = iv ? *(const float4*)(arow + ak8)     : z4;
    float4 ra1 = iv ? *(const float4*)(arow + ak8 + 4) : z4;
    float4 rb0 = (bk      < NN) ? *(const float4*)(g_XL + (size_t)bk * DD + h * CC + n0 + bn)        : z4;
    float4 rb1 = (bk + 16 < NN) ? *(const float4*)(g_XL + (size_t)(bk + 16) * DD + h * CC + n0 + bn) : z4;

    for (int k0 = 0; k0 < NPJ; k0 += 32) {
        As[ak8 + 0][ar] = ra0.x; As[ak8 + 1][ar] = ra0.y;
        As[ak8 + 2][ar] = ra0.z; As[ak8 + 3][ar] = ra0.w;
        As[ak8 + 4][ar] = ra1.x; As[ak8 + 5][ar] = ra1.y;
        As[ak8 + 6][ar] = ra1.z; As[ak8 + 7][ar] = ra1.w;
        *(float4*)&Bs[bk][bn]      = rb0;
        *(float4*)&Bs[bk + 16][bn] = rb1;
        __syncthreads();

        if (k0 + 32 < NPJ) {
            const int kb = k0 + 32;
            ra0 = iv ? *(const float4*)(arow + kb + ak8)     : z4;
            ra1 = iv ? *(const float4*)(arow + kb + ak8 + 4) : z4;
            int j0n = kb + bk, j1n = kb + bk + 16;
            rb0 = (j0n < NN) ? *(const float4*)(g_XL + (size_t)j0n * DD + h * CC + n0 + bn) : z4;
            rb1 = (j1n < NN) ? *(const float4*)(g_XL + (size_t)j1n * DD + h * CC + n0 + bn) : z4;
        }

#pragma unroll
        for (int k = 0; k < 32; k++) {
            float2 ap = *(const float2*)&As[k][ty * 2];
            float a0 = ap.x, a1 = ap.y;
            float4 v0 = *(const float4*)&Bs[k][tx * 4];
            acc[0][0] = fmaf(a0, v0.x, acc[0][0]);
            acc[0][1] = fmaf(a0, v0.y, acc[0][1]);
            acc[0][2] = fmaf(a0, v0.z, acc[0][2]);
            acc[0][3] = fmaf(a0, v0.w, acc[0][3]);
            acc[1][0] = fmaf(a1, v0.x, acc[1][0]);
            acc[1][1] = fmaf(a1, v0.y, acc[1][1]);
            acc[1][2] = fmaf(a1, v0.z, acc[1][2]);
            acc[1][3] = fmaf(a1, v0.w, acc[1][3]);
        }
        __syncthreads();
    }

#pragma unroll
    for (int ii = 0; ii < 2; ii++) {
        int i = i0 + ty * 2 + ii;
        if (i >= NN) continue;
        float* orow = OUT + (size_t)i * DD + h * CC + n0;
        const float* bp = bias + h * CC + n0;
        float4 o0 = {acc[ii][0], acc[ii][1], acc[ii][2], acc[ii][3]};
        float4 b0 = *(const float4*)(bp + tx * 4);
        o0.x += b0.x; o0.y += b0.y; o0.z += b0.z; o0.w += b0.w;
        if (relu) {
            o0.x = fmaxf(o0.x, 0.f); o0.y = fmaxf(o0.y, 0.f);
            o0.z = fmaxf(o0.z, 0.f); o0.w = fmaxf(o0.w, 0.f);
        }
        *(float4*)(orow + tx * 4) = o0;
    }
}

// ---------------------------------------------------------------------------
// Pooling (8 blocks x 128): avg[d] = sum_i w_i * H2[i][d]; re-zeroes g_cnt.
// ---------------------------------------------------------------------------
__global__ void k_pool() {
    int d = blockIdx.x * blockDim.x + threadIdx.x;
    float s = 0.f;
#pragma unroll 8
    for (int i = 0; i < NN - 1; i++) s += g_H2[i * DD + d];
    s = s * (1.f / 300.f) + g_H2[(NN - 1) * DD + d] * (1.f / 3.f);
    g_avg[d] = s;
    for (int idx = d; idx < NN * NPJ; idx += 1024) g_cnt[idx] = 0;
}

// ---------------------------------------------------------------------------
// Classifier: out[c] = avg . clfW[c] + clfb[c]
// ---------------------------------------------------------------------------
__global__ void k_clf(const float* __restrict__ W, const float* __restrict__ b,
                      float* __restrict__ out) {
    __shared__ float red0[8], red1[8];
    int tid = threadIdx.x;
    float p0 = 0.f, p1 = 0.f;
    for (int d = tid; d < DD; d += 256) {
        float a = g_avg[d];
        p0 = fmaf(a, W[d], p0);
        p1 = fmaf(a, W[DD + d], p1);
    }
    for (int o = 16; o; o >>= 1) {
        p0 += __shfl_xor_sync(0xffffffffu, p0, o);
        p1 += __shfl_xor_sync(0xffffffffu, p1, o);
    }
    if ((tid & 31) == 0) { red0[tid >> 5] = p0; red1[tid >> 5] = p1; }
    __syncthreads();
    if (tid == 0) {
        float s0 = 0.f, s1 = 0.f;
        for (int w = 0; w < 8; w++) { s0 += red0[w]; s1 += red1[w]; }
        out[0] = s0 + b[0];
        out[1] = s1 + b[1];
    }
}

// ---------------------------------------------------------------------------
extern "C" void kernel_launch(void* const* d_in, const int* in_sizes, int n_in,
                              void* d_out, int out_size) {
    const float* x     = (const float*)d_in[0];
    const int*   ebuf  = (const int*)  d_in[1];
    const float* W1l   = (const float*)d_in[2];
    const float* b1l   = (const float*)d_in[3];
    const float* W1r   = (const float*)d_in[4];
    const float* b1r   = (const float*)d_in[5];
    const float* att1  = (const float*)d_in[6];
    const float* bias1 = (const float*)d_in[7];
    const float* W2l   = (const float*)d_in[8];
    const float* b2l   = (const float*)d_in[9];
    const float* W2r   = (const float*)d_in[10];
    const float* b2r   = (const float*)d_in[11];
    const float* att2  = (const float*)d_in[12];
    const float* bias2 = (const float*)d_in[13];
    const float* clfW  = (const float*)d_in[14];
    const float* clfb  = (const float*)d_in[15];
    float* out = (float*)d_out;

    dim3 gg1(4, 16, 3);         // GEMM l/r + edge-count plane (layer 1)
    dim3 gg2(4, 16, 2);         // GEMM l/r (layer 2)
    dim3 gs(7, 7, HH);          // score
    dim3 gn(26, HH);            // norm
    dim3 ga(7, 4, HH);          // agg

    // layer 1 (edge counting fused into the GEMM launch)
    k_gemm_mma<<<gg1, 256>>>(x, W1l, b1l, W1r, b1r, ebuf);
    k_score   <<<gs, 128>>>(att1);
    k_norm    <<<gn, 256>>>();
    k_aggemm  <<<ga, 128>>>(bias1, /*relu=*/1, /*dst=*/0);

    // layer 2
    k_gemm_mma<<<gg2, 256>>>(nullptr, W2l, b2l, W2r, b2r, nullptr);
    k_score   <<<gs, 128>>>(att2);
    k_norm    <<<gn, 256>>>();
    k_aggemm  <<<ga, 128>>>(bias2, /*relu=*/0, /*dst=*/1);

    // pooling (+ g_cnt reset) and classifier
    k_pool<<<8, 128>>>();
    k_clf <<<1, 256>>>(clfW, clfb, out);
}

// round 17
// speedup vs baseline: 1.2102x; 1.0585x over previous
#include <cuda_runtime.h>
#include <cuda_bf16.h>
#include <mma.h>
#include <math.h>
#include <float.h>
#include <stdint.h>

using namespace nvcuda;

// ----------------------------------------------------------------------------
// GATv2 x2 + mean-pool + classifier, dense-pair formulation.
// N=201, E=40200 (+201 self loops), D=1024 = 8 heads x 128 ch.
// One-shot bf16 hi/lo conversion (k_cvt, count fused). GEMM: WMMA bf16 x3
// products with 3-stage cp.async pipeline. Score 32x32 BK32; softmax pass;
// aggregation fp32 GEMM 32x32 BK32 (layer 1 writes bf16 H twin).
// ----------------------------------------------------------------------------

#define NN   201
#define EE   40200
#define DD   1024
#define HH   8
#define CC   128
#define NPJ  224
#define NPAD 204
#define NPX  256            // padded rows for bf16 X operands (GEMM loads rows < 256)

// -------- scratch (device globals; no allocation allowed) -------------------
__device__ __align__(16) float g_XL[NPAD * DD];
__device__ __align__(16) float g_XR[NPAD * DD];
__device__ __align__(16) float g_H2[NPAD * DD];
__device__ __align__(16) float g_S [HH * NN * NPJ];
__device__ int   g_cnt[NN * NPJ];     // statically zero; re-zeroed by k_pool
__device__ __align__(16) float g_avg[DD];
// bf16 hi/lo operands: W order [W1l, W1r, W2l, W2r]; X = x (L1), H (L2)
__device__ __align__(16) __nv_bfloat16 g_Wh[4 * DD * DD];
__device__ __align__(16) __nv_bfloat16 g_Wl[4 * DD * DD];
__device__ __align__(16) __nv_bfloat16 g_Xh[NPX * DD];    // rows >= NN stay 0
__device__ __align__(16) __nv_bfloat16 g_Xl[NPX * DD];

__device__ __forceinline__ void cvt8(const float* v, __nv_bfloat16* hi, __nv_bfloat16* lo) {
#pragma unroll
    for (int e = 0; e < 8; e++) {
        hi[e] = __float2bfloat16(v[e]);
        lo[e] = __float2bfloat16(v[e] - __bfloat162float(hi[e]));
    }
}

__device__ __forceinline__ void cpa16(void* dst, const void* src) {
    uint32_t d = (uint32_t)__cvta_generic_to_shared(dst);
    asm volatile("cp.async.cg.shared.global [%0], [%1], 16;" :: "r"(d), "l"(src));
}
#define CP_COMMIT() asm volatile("cp.async.commit_group;" ::: "memory")
#define CP_WAIT2()  asm volatile("cp.async.wait_group 2;" ::: "memory")
#define CP_WAIT0()  asm volatile("cp.async.wait_group 0;" ::: "memory")

// ---------------------------------------------------------------------------
// k_cvt: one launch at graph start.
//   [0,2048)      : W1l/W1r/W2l/W2r fp32 -> bf16 hi/lo (512 blocks each)
//   [2048,2149)   : x -> g_Xh/g_Xl
//   [2149,2213)   : edge counting
// ---------------------------------------------------------------------------
#define WCVT_BLK 2048
#define XCVT_BLK 101
#define CNT_BLK  64
#define CVT_GRID (WCVT_BLK + XCVT_BLK + CNT_BLK)

__global__ void __launch_bounds__(256) k_cvt(
    const float* __restrict__ x,
    const float* __restrict__ W1l, const float* __restrict__ W1r,
    const float* __restrict__ W2l, const float* __restrict__ W2r,
    const int* __restrict__ eb)
{
    const int bid = blockIdx.x;
    const int tid = threadIdx.x;

    if (bid < WCVT_BLK) {
        const int wsel = bid >> 9;
        const float* src = (wsel == 0) ? W1l : (wsel == 1) ? W1r
                         : (wsel == 2) ? W2l : W2r;
        const size_t off = (((size_t)(bid & 511)) * 256 + tid) * 8;
        float v[8];
        *(float4*)&v[0] = *(const float4*)(src + off);
        *(float4*)&v[4] = *(const float4*)(src + off + 4);
        __nv_bfloat16 hi[8], lo[8];
        cvt8(v, hi, lo);
        const size_t base = (size_t)wsel * DD * DD + off;
        *(uint4*)(g_Wh + base) = *(uint4*)hi;
        *(uint4*)(g_Wl + base) = *(uint4*)lo;
    } else if (bid < WCVT_BLK + XCVT_BLK) {
        const size_t off = (((size_t)(bid - WCVT_BLK)) * 256 + tid) * 8;
        if (off < (size_t)NN * DD) {
            float v[8];
            *(float4*)&v[0] = *(const float4*)(x + off);
            *(float4*)&v[4] = *(const float4*)(x + off + 4);
            __nv_bfloat16 hi[8], lo[8];
            cvt8(v, hi, lo);
            *(uint4*)(g_Xh + off) = *(uint4*)hi;
            *(uint4*)(g_Xl + off) = *(uint4*)lo;
        }
    } else {
        __shared__ int st_s;
        if (tid == 0) {
            int st = 2;  // int64: odd words zero for values < 2^31
            for (int e = 0; e < 64; e++)
                if (eb[2 * e + 1] != 0) { st = 1; break; }
            st_s = st;
        }
        __syncthreads();
        const int st = st_s;
        const int cb = bid - WCVT_BLK - XCVT_BLK;
        for (int e = cb * 256 + tid; e < EE + NN; e += CNT_BLK * 256) {
            if (e < EE) {
                int src = eb[e * st];
                int dst = eb[(EE + e) * st];
                atomicAdd(&g_cnt[dst * NPJ + src], 1);
            } else {
                int v = e - EE;
                atomicAdd(&g_cnt[v * NPJ + v], 1);
            }
        }
    }
}

// ---------------------------------------------------------------------------
// WMMA bf16 GEMM, 3-stage cp.async pipeline, pre-converted operands.
// O[m][n] = sum_k X[m][k]*W[n][k] + b[n]; grid (4 m, 16 n, 2 sides) = 128.
// 64x64 tile, 256 threads, BK=64, 16 chunks. Stage = Ah|Al|Bh|Bl, 36864 B.
// ---------------------------------------------------------------------------
#define G_LDM 72                       // 64 k + 8 pad (bf16)
#define ARR_ELEMS (64 * G_LDM)         // one array, one stage
#define STG_ELEMS (4 * ARR_ELEMS)      // 18432 elems = 36864 B
#define GSMEM_BYTES (3 * STG_ELEMS * 2)

__global__ void __launch_bounds__(256) k_gemm_cp(
    int layer, const float* __restrict__ bl, const float* __restrict__ br)
{
    extern __shared__ __align__(16) char smem[];

    const int side = blockIdx.z;
    const float* b = side ? br : bl;
    float*       O = side ? g_XR : g_XL;
    const size_t wbase = ((size_t)((layer << 1) | side)) * DD * DD;
    const int m0 = blockIdx.x * 64;
    const int n0 = blockIdx.y * 64;

    const int tid = threadIdx.x;
    const int wid = tid >> 5;
    const int wm  = wid >> 2;
    const int wn  = wid & 3;

    wmma::fragment<wmma::accumulator, 16, 16, 16, float> c0, c1;
    wmma::fill_fragment(c0, 0.f);
    wmma::fill_fragment(c1, 0.f);

    // issue one BK=64 chunk into stage slot s (8 cp.async per thread)
    auto issue = [&](int kc, int s) {
        __nv_bfloat16* Ah = (__nv_bfloat16*)smem + s * STG_ELEMS;
        __nv_bfloat16* Al = Ah + ARR_ELEMS;
        __nv_bfloat16* Bh = Al + ARR_ELEMS;
        __nv_bfloat16* Bl = Bh + ARR_ELEMS;
        const int kb = kc * 64;
#pragma unroll
        for (int rep = 0; rep < 2; rep++) {
            const int id  = tid + rep * 256;
            const int row = id >> 3;
            const int cq  = (id & 7) * 8;
            const size_t goA = (size_t)(m0 + row) * DD + kb + cq;
            const size_t goB = wbase + (size_t)(n0 + row) * DD + kb + cq;
            const int    so  = row * G_LDM + cq;
            cpa16(Ah + so, g_Xh + goA);
            cpa16(Al + so, g_Xl + goA);
            cpa16(Bh + so, g_Wh + goB);
            cpa16(Bl + so, g_Wl + goB);
        }
        CP_COMMIT();
    };

    issue(0, 0);
    issue(1, 1);

    const int NC = DD / 64;    // 16
    for (int kc = 0; kc < NC; kc++) {
        if (kc + 2 < NC) { issue(kc + 2, (kc + 2) % 3); CP_WAIT2(); }
        else             { CP_WAIT0(); }
        __syncthreads();

        {
            const int s = kc % 3;
            __nv_bfloat16* Ah = (__nv_bfloat16*)smem + s * STG_ELEMS;
            __nv_bfloat16* Al = Ah + ARR_ELEMS;
            __nv_bfloat16* Bh = Al + ARR_ELEMS;
            __nv_bfloat16* Bl = Bh + ARR_ELEMS;
#pragma unroll
            for (int ks = 0; ks < 4; ks++) {
                const int kk = ks * 16;
                wmma::fragment<wmma::matrix_b, 16, 16, 16, __nv_bfloat16, wmma::col_major> fbh, fbl;
                wmma::load_matrix_sync(fbh, Bh + (wn * 16) * G_LDM + kk, G_LDM);
                wmma::load_matrix_sync(fbl, Bl + (wn * 16) * G_LDM + kk, G_LDM);

                wmma::fragment<wmma::matrix_a, 16, 16, 16, __nv_bfloat16, wmma::row_major> fah, fal;
                wmma::load_matrix_sync(fah, Ah + (wm * 32) * G_LDM + kk, G_LDM);
                wmma::load_matrix_sync(fal, Al + (wm * 32) * G_LDM + kk, G_LDM);
                wmma::mma_sync(c0, fah, fbh, c0);
                wmma::mma_sync(c0, fah, fbl, c0);
                wmma::mma_sync(c0, fal, fbh, c0);
                wmma::load_matrix_sync(fah, Ah + (wm * 32 + 16) * G_LDM + kk, G_LDM);
                wmma::load_matrix_sync(fal, Al + (wm * 32 + 16) * G_LDM + kk, G_LDM);
                wmma::mma_sync(c1, fah, fbh, c1);
                wmma::mma_sync(c1, fah, fbl, c1);
                wmma::mma_sync(c1, fal, fbh, c1);
            }
        }
        __syncthreads();   // protect slot kc%3 before reuse at kc+3
    }

    // epilogue via smem (aliases stage buffers), fused bias
    float* Cs = (float*)smem;          // 64 x 72 fp32 = 18432 B
    wmma::store_matrix_sync(Cs + (wm * 32) * G_LDM + wn * 16, c0, G_LDM, wmma::mem_row_major);
    wmma::store_matrix_sync(Cs + (wm * 32 + 16) * G_LDM + wn * 16, c1, G_LDM, wmma::mem_row_major);
    __syncthreads();

    const int lr = tid >> 2;
    const int m  = m0 + lr;
    if (m < NN) {
        const int cb = (tid & 3) * 16;
        float* orow = O + (size_t)m * DD + n0 + cb;
        const float* bp = b + n0 + cb;
#pragma unroll
        for (int c4 = 0; c4 < 16; c4 += 4) {
            float4 vv = *(float4*)&Cs[lr * G_LDM + cb + c4];
            float4 bb = *(const float4*)(bp + c4);
            vv.x += bb.x; vv.y += bb.y; vv.z += bb.z; vv.w += bb.w;
            *(float4*)(orow + c4) = vv;
        }
    }
}

// ---------------------------------------------------------------------------
// Dense pairwise scores, 32x32 tiles / 128 threads, BK=32, microtile 2i x 4j.
//   S[h,i,j] = P'(0.4*att) + 1.5*AL'   (AR term cancels in the softmax)
// grid = (7, 7, 8) = 392 blocks.
// ---------------------------------------------------------------------------
__global__ void __launch_bounds__(128) k_score(const float* __restrict__ att) {
    const int h   = blockIdx.z;
    const int i0  = blockIdx.x * 32;
    const int j0  = blockIdx.y * 32;
    const int tid = threadIdx.x;
    const int tx  = tid & 7;
    const int ty  = tid >> 3;
    const int lrow = tid >> 2;
    const int lq8  = (tid & 3) << 3;

    __shared__ __align__(16) float att_s[CC];   // 0.4 * att
    __shared__ float AL_s[32];
    __shared__ float alp[32][4];
    __shared__ float As[32][32];
    __shared__ float Bs[32][32];

    if (tid < 32) {
        float4 a = *(const float4*)(att + h * CC + tid * 4);
        a.x *= 0.4f; a.y *= 0.4f; a.z *= 0.4f; a.w *= 0.4f;
        *(float4*)&att_s[tid * 4] = a;
    }
    __syncthreads();

    {
        int jj = tid >> 2, part = tid & 3;
        int j  = j0 + jj;
        float s = 0.f;
        if (j < NN) {
            const float4* xp4 = (const float4*)(g_XL + (size_t)j * DD + h * CC + part * 32);
#pragma unroll
            for (int q = 0; q < 8; q++) {
                float4 xv = xp4[q];
                const float* ap = att_s + part * 32 + q * 4;
                s = fmaf(ap[0], xv.x, s);
                s = fmaf(ap[1], xv.y, s);
                s = fmaf(ap[2], xv.z, s);
                s = fmaf(ap[3], xv.w, s);
            }
        }
        alp[jj][part] = s;
    }
    __syncthreads();
    if (tid < 32) AL_s[tid] = alp[tid][0] + alp[tid][1] + alp[tid][2] + alp[tid][3];
    __syncthreads();

    const int  gi = i0 + lrow;
    const int  gj = j0 + lrow;
    const bool iv = (gi < NN);
    const bool jv = (gj < NN);
    const float* xrp = g_XR + (size_t)gi * DD + h * CC;
    const float* xlp = g_XL + (size_t)gj * DD + h * CC;

    float acc[2][4];
#pragma unroll
    for (int i = 0; i < 2; i++)
#pragma unroll
        for (int j = 0; j < 4; j++) acc[i][j] = 0.f;

    const float4 z4 = make_float4(0, 0, 0, 0);
    float4 ra0 = iv ? *(const float4*)(xrp + lq8)     : z4;
    float4 ra1 = iv ? *(const float4*)(xrp + lq8 + 4) : z4;
    float4 rb0 = jv ? *(const float4*)(xlp + lq8)     : z4;
    float4 rb1 = jv ? *(const float4*)(xlp + lq8 + 4) : z4;

    for (int k0 = 0; k0 < CC; k0 += 32) {
        As[lq8 + 0][lrow] = ra0.x; As[lq8 + 1][lrow] = ra0.y;
        As[lq8 + 2][lrow] = ra0.z; As[lq8 + 3][lrow] = ra0.w;
        As[lq8 + 4][lrow] = ra1.x; As[lq8 + 5][lrow] = ra1.y;
        As[lq8 + 6][lrow] = ra1.z; As[lq8 + 7][lrow] = ra1.w;
        Bs[lq8 + 0][lrow] = rb0.x; Bs[lq8 + 1][lrow] = rb0.y;
        Bs[lq8 + 2][lrow] = rb0.z; Bs[lq8 + 3][lrow] = rb0.w;
        Bs[lq8 + 4][lrow] = rb1.x; Bs[lq8 + 5][lrow] = rb1.y;
        Bs[lq8 + 6][lrow] = rb1.z; Bs[lq8 + 7][lrow] = rb1.w;
        __syncthreads();

        if (k0 + 32 < CC) {
            const int kb = k0 + 32;
            ra0 = iv ? *(const float4*)(xrp + kb + lq8)     : z4;
            ra1 = iv ? *(const float4*)(xrp + kb + lq8 + 4) : z4;
            rb0 = jv ? *(const float4*)(xlp + kb + lq8)     : z4;
            rb1 = jv ? *(const float4*)(xlp + kb + lq8 + 4) : z4;
        }

#pragma unroll
        for (int k = 0; k < 32; k++) {
            float a0 = As[k][ty * 2 + 0];
            float a1 = As[k][ty * 2 + 1];
            float4 b4 = *(const float4*)&Bs[k][tx << 2];
            float bv[4] = {b4.x, b4.y, b4.z, b4.w};
            float ac = att_s[k0 + k];
#pragma unroll
            for (int j = 0; j < 4; j++) {
                float t0 = a0 + bv[j];
                float t1 = a1 + bv[j];
                acc[0][j] = fmaf(ac, fabsf(t0), acc[0][j]);
                acc[1][j] = fmaf(ac, fabsf(t1), acc[1][j]);
            }
        }
        __syncthreads();
    }

#pragma unroll
    for (int ii = 0; ii < 2; ii++) {
        int i = i0 + ty * 2 + ii;
        if (i >= NN) continue;
        float* row = g_S + (size_t)(h * NN + i) * NPJ;
#pragma unroll
        for (int jj = 0; jj < 4; jj++) {
            int j = j0 + (tx << 2) + jj;
            if (j < NN)
                row[j] = fmaf(1.5f, AL_s[(tx << 2) + jj], acc[ii][jj]);
        }
    }
}

// ---------------------------------------------------------------------------
// Alpha normalization in place (vectorized): g_S row -> softmax alphas.
// grid (26, 8), 256 threads; warp per destination row.
// ---------------------------------------------------------------------------
__global__ void __launch_bounds__(256) k_norm() {
    const int h    = blockIdx.y;
    const int i    = blockIdx.x * 8 + (threadIdx.x >> 5);
    const int lane = threadIdx.x & 31;
    if (i >= NN) return;

    float*     srow = g_S + (size_t)(h * NN + i) * NPJ;
    const int* crow = g_cnt + i * NPJ;

    const bool two = (lane < 24);
    float4 s0 = *(const float4*)(srow + lane * 4);
    int4   c0 = *(const int4*)(crow + lane * 4);
    float4 s1 = make_float4(0, 0, 0, 0);
    int4   c1 = make_int4(0, 0, 0, 0);
    if (two) {
        s1 = *(const float4*)(srow + 128 + lane * 4);
        c1 = *(const int4*)(crow + 128 + lane * 4);
    }

    float sv[8], cv[8];
    sv[0] = (c0.x > 0) ? s0.x : -1e30f; cv[0] = (float)c0.x;
    sv[1] = (c0.y > 0) ? s0.y : -1e30f; cv[1] = (float)c0.y;
    sv[2] = (c0.z > 0) ? s0.z : -1e30f; cv[2] = (float)c0.z;
    sv[3] = (c0.w > 0) ? s0.w : -1e30f; cv[3] = (float)c0.w;
    sv[4] = (c1.x > 0) ? s1.x : -1e30f; cv[4] = (float)c1.x;
    sv[5] = (c1.y > 0) ? s1.y : -1e30f; cv[5] = (float)c1.y;
    sv[6] = (c1.z > 0) ? s1.z : -1e30f; cv[6] = (float)c1.z;
    sv[7] = (c1.w > 0) ? s1.w : -1e30f; cv[7] = (float)c1.w;

    float mx = -FLT_MAX;
#pragma unroll
    for (int t = 0; t < 8; t++) mx = fmaxf(mx, sv[t]);
#pragma unroll
    for (int o = 16; o; o >>= 1) mx = fmaxf(mx, __shfl_xor_sync(0xffffffffu, mx, o));

    float ev[8];
    float ds = 0.f;
#pragma unroll
    for (int t = 0; t < 8; t++) { ev[t] = cv[t] * __expf(sv[t] - mx); ds += ev[t]; }
#pragma unroll
    for (int o = 16; o; o >>= 1) ds += __shfl_xor_sync(0xffffffffu, ds, o);
    float inv = 1.f / (ds + 1e-16f);

    float4 a0 = {ev[0] * inv, ev[1] * inv, ev[2] * inv, ev[3] * inv};
    *(float4*)(srow + lane * 4) = a0;
    if (two) {
        float4 a1 = {ev[4] * inv, ev[5] * inv, ev[6] * inv, ev[7] * inv};
        *(float4*)(srow + 128 + lane * 4) = a1;
    }
}

// ---------------------------------------------------------------------------
// Aggregation GEMM: OUT[i][h*CC+n] = sum_j alpha[h,i,j] * XL[j][h*CC+n] + bias
// Tile 32i x 32n, K=NPJ BK=32; 128 threads, microtile 2i x 4n; grid (7,4,8).
// Layer 1 also writes the bf16 hi/lo twin of H into g_Xh/g_Xl for GEMM-2.
// ---------------------------------------------------------------------------
__global__ void __launch_bounds__(128) k_aggemm(const float* __restrict__ bias,
                                                int relu, int dst_sel) {
    float*    OUT = g_H2;
    const int h   = blockIdx.z;
    const int i0  = blockIdx.x * 32;
    const int n0  = blockIdx.y * 32;
    const int tid = threadIdx.x;
    const int tx  = tid & 7;
    const int ty  = tid >> 3;

    __shared__ float As[32][32];
    __shared__ float Bs[32][32];

    const int  ar  = tid & 31;
    const int  ak8 = (tid >> 5) << 3;
    const bool iv  = (i0 + ar) < NN;
    const float* arow = g_S + (size_t)(h * NN + i0 + ar) * NPJ;

    const int bk = tid >> 3;
    const int bn = (tid & 7) << 2;

    float acc[2][4];
#pragma unroll
    for (int i = 0; i < 2; i++)
#pragma unroll
        for (int j = 0; j < 4; j++) acc[i][j] = 0.f;

    const float4 z4 = make_float4(0, 0, 0, 0);
    float4 ra0 = iv ? *(const float4*)(arow + ak8)     : z4;
    float4 ra1 = iv ? *(const float4*)(arow + ak8 + 4) : z4;
    float4 rb0 = (bk      < NN) ? *(const float4*)(g_XL + (size_t)bk * DD + h * CC + n0 + bn)        : z4;
    float4 rb1 = (bk + 16 < NN) ? *(const float4*)(g_XL + (size_t)(bk + 16) * DD + h * CC + n0 + bn) : z4;

    for (int k0 = 0; k0 < NPJ; k0 += 32) {
        As[ak8 + 0][ar] = ra0.x; As[ak8 + 1][ar] = ra0.y;
        As[ak8 + 2][ar] = ra0.z; As[ak8 + 3][ar] = ra0.w;
        As[ak8 + 4][ar] = ra1.x; As[ak8 + 5][ar] = ra1.y;
        As[ak8 + 6][ar] = ra1.z; As[ak8 + 7][ar] = ra1.w;
        *(float4*)&Bs[bk][bn]      = rb0;
        *(float4*)&Bs[bk + 16][bn] = rb1;
        __syncthreads();

        if (k0 + 32 < NPJ) {
            const int kb = k0 + 32;
            ra0 = iv ? *(const float4*)(arow + kb + ak8)     : z4;
            ra1 = iv ? *(const float4*)(arow + kb + ak8 + 4) : z4;
            int j0n = kb + bk, j1n = kb + bk + 16;
            rb0 = (j0n < NN) ? *(const float4*)(g_XL + (size_t)j0n * DD + h * CC + n0 + bn) : z4;
            rb1 = (j1n < NN) ? *(const float4*)(g_XL + (size_t)j1n * DD + h * CC + n0 + bn) : z4;
        }

#pragma unroll
        for (int k = 0; k < 32; k++) {
            float2 ap = *(const float2*)&As[k][ty * 2];
            float a0 = ap.x, a1 = ap.y;
            float4 v0 = *(const float4*)&Bs[k][tx * 4];
            acc[0][0] = fmaf(a0, v0.x, acc[0][0]);
            acc[0][1] = fmaf(a0, v0.y, acc[0][1]);
            acc[0][2] = fmaf(a0, v0.z, acc[0][2]);
            acc[0][3] = fmaf(a0, v0.w, acc[0][3]);
            acc[1][0] = fmaf(a1, v0.x, acc[1][0]);
            acc[1][1] = fmaf(a1, v0.y, acc[1][1]);
            acc[1][2] = fmaf(a1, v0.z, acc[1][2]);
            acc[1][3] = fmaf(a1, v0.w, acc[1][3]);
        }
        __syncthreads();
    }

#pragma unroll
    for (int ii = 0; ii < 2; ii++) {
        int i = i0 + ty * 2 + ii;
        if (i >= NN) continue;
        const int col = h * CC + n0 + tx * 4;
        const float* bp = bias + h * CC + n0;
        float4 o0 = {acc[ii][0], acc[ii][1], acc[ii][2], acc[ii][3]};
        float4 b0 = *(const float4*)(bp + tx * 4);
        o0.x += b0.x; o0.y += b0.y; o0.z += b0.z; o0.w += b0.w;
        if (relu) {
            o0.x = fmaxf(o0.x, 0.f); o0.y = fmaxf(o0.y, 0.f);
            o0.z = fmaxf(o0.z, 0.f); o0.w = fmaxf(o0.w, 0.f);
        }
        *(float4*)(OUT + (size_t)i * DD + col) = o0;
        if (!dst_sel) {
            float v[4] = {o0.x, o0.y, o0.z, o0.w};
            __nv_bfloat16 hi[4], lo[4];
#pragma unroll
            for (int e = 0; e < 4; e++) {
                hi[e] = __float2bfloat16(v[e]);
                lo[e] = __float2bfloat16(v[e] - __bfloat162float(hi[e]));
            }
            *(uint2*)(g_Xh + (size_t)i * DD + col) = *(uint2*)hi;
            *(uint2*)(g_Xl + (size_t)i * DD + col) = *(uint2*)lo;
        }
    }
}

// ---------------------------------------------------------------------------
// Pooling (8 blocks x 128): avg[d] = sum_i w_i * H2[i][d]; re-zeroes g_cnt.
// ---------------------------------------------------------------------------
__global__ void k_pool() {
    int d = blockIdx.x * blockDim.x + threadIdx.x;
    float s = 0.f;
#pragma unroll 8
    for (int i = 0; i < NN - 1; i++) s += g_H2[i * DD + d];
    s = s * (1.f / 300.f) + g_H2[(NN - 1) * DD + d] * (1.f / 3.f);
    g_avg[d] = s;
    for (int idx = d; idx < NN * NPJ; idx += 1024) g_cnt[idx] = 0;
}

// ---------------------------------------------------------------------------
// Classifier: out[c] = avg . clfW[c] + clfb[c]
// ---------------------------------------------------------------------------
__global__ void k_clf(const float* __restrict__ W, const float* __restrict__ b,
                      float* __restrict__ out) {
    __shared__ float red0[8], red1[8];
    int tid = threadIdx.x;
    float p0 = 0.f, p1 = 0.f;
    for (int d = tid; d < DD; d += 256) {
        float a = g_avg[d];
        p0 = fmaf(a, W[d], p0);
        p1 = fmaf(a, W[DD + d], p1);
    }
    for (int o = 16; o; o >>= 1) {
        p0 += __shfl_xor_sync(0xffffffffu, p0, o);
        p1 += __shfl_xor_sync(0xffffffffu, p1, o);
    }
    if ((tid & 31) == 0) { red0[tid >> 5] = p0; red1[tid >> 5] = p1; }
    __syncthreads();
    if (tid == 0) {
        float s0 = 0.f, s1 = 0.f;
        for (int w = 0; w < 8; w++) { s0 += red0[w]; s1 += red1[w]; }
        out[0] = s0 + b[0];
        out[1] = s1 + b[1];
    }
}

// ---------------------------------------------------------------------------
extern "C" void kernel_launch(void* const* d_in, const int* in_sizes, int n_in,
                              void* d_out, int out_size) {
    const float* x     = (const float*)d_in[0];
    const int*   ebuf  = (const int*)  d_in[1];
    const float* W1l   = (const float*)d_in[2];
    const float* b1l   = (const float*)d_in[3];
    const float* W1r   = (const float*)d_in[4];
    const float* b1r   = (const float*)d_in[5];
    const float* att1  = (const float*)d_in[6];
    const float* bias1 = (const float*)d_in[7];
    const float* W2l   = (const float*)d_in[8];
    const float* b2l   = (const float*)d_in[9];
    const float* W2r   = (const float*)d_in[10];
    const float* b2r   = (const float*)d_in[11];
    const float* att2  = (const float*)d_in[12];
    const float* bias2 = (const float*)d_in[13];
    const float* clfW  = (const float*)d_in[14];
    const float* clfb  = (const float*)d_in[15];
    float* out = (float*)d_out;

    cudaFuncSetAttribute(k_gemm_cp, cudaFuncAttributeMaxDynamicSharedMemorySize,
                         GSMEM_BYTES);

    dim3 gg(4, 16, 2);          // GEMM: m-tiles x n-tiles x {l,r}
    dim3 gs(7, 7, HH);          // score
    dim3 gn(26, HH);            // norm
    dim3 ga(7, 4, HH);          // agg

    // convert weights + x to bf16 hi/lo; count edges (one launch)
    k_cvt<<<CVT_GRID, 256>>>(x, W1l, W1r, W2l, W2r, ebuf);

    // layer 1
    k_gemm_cp<<<gg, 256, GSMEM_BYTES>>>(0, b1l, b1r);
    k_score  <<<gs, 128>>>(att1);
    k_norm   <<<gn, 256>>>();
    k_aggemm <<<ga, 128>>>(bias1, /*relu=*/1, /*dst=*/0);   // writes bf16 H

    // layer 2
    k_gemm_cp<<<gg, 256, GSMEM_BYTES>>>(1, b2l, b2r);
    k_score  <<<gs, 128>>>(att2);
    k_norm   <<<gn, 256>>>();
    k_aggemm <<<ga, 128>>>(bias2, /*relu=*/0, /*dst=*/1);

    // pooling (+ g_cnt reset) and classifier
    k_pool<<<8, 128>>>();
    k_clf <<<1, 256>>>(clfW, clfb, out);
}